// round 1
// baseline (speedup 1.0000x reference)
#include <cuda_runtime.h>
#include <math.h>

#define N_NODES 100000
#define N_EDGES 800000

// ---------------- device scratch (allocation-free rule: __device__ globals) ----------------
__device__ float g_h[(size_t)N_NODES * 128];     // node features (updated per block)
__device__ float g_ea[(size_t)N_EDGES * 128];    // edge features (built once per launch)
__device__ float g_q[(size_t)N_NODES * 128];
__device__ float g_k[(size_t)N_NODES * 128];
__device__ float g_v[(size_t)N_NODES * 128];
__device__ float g_skip[(size_t)N_NODES * 128];
__device__ float g_numer[(size_t)N_NODES * 128];
__device__ float g_denom[(size_t)N_NODES * 8];

// ---------------- helpers ----------------
__device__ __forceinline__ void fma2(unsigned long long &d, unsigned long long a, unsigned long long b) {
    asm("fma.rn.f32x2 %0, %1, %2, %0;" : "+l"(d) : "l"(a), "l"(b));
}
__device__ __forceinline__ unsigned long long pack2(float lo, float hi) {
    unsigned long long r;
    asm("mov.b64 %0, {%1, %2};" : "=l"(r) : "f"(lo), "f"(hi));
    return r;
}
__device__ __forceinline__ float2 unpack2(unsigned long long v) {
    float lo, hi;
    asm("mov.b64 {%0, %1}, %2;" : "=f"(lo), "=f"(hi) : "l"(v));
    return make_float2(lo, hi);
}
__device__ __forceinline__ void red_add4(float* addr, float a, float b, float c, float d) {
    asm volatile("red.global.add.v4.f32 [%0], {%1, %2, %3, %4};"
                 :: "l"(addr), "f"(a), "f"(b), "f"(c), "f"(d) : "memory");
}

// Sinusoidal PE value: pe[t][c], c in [0,16): j=c/2, even->sin, odd->cos
__device__ __forceinline__ float pe_val(int t, int c) {
    int j = c >> 1;
    float freq = expf(-logf(10000.0f) * (float)(2 * j) * (1.0f / 16.0f));
    float ang = (float)t * freq;
    return (c & 1) ? cosf(ang) : sinf(ang);
}

// ---------------- builders ----------------
__global__ void build_h_kernel(const float* __restrict__ x, const int* __restrict__ nlu) {
    int idx = blockIdx.x * blockDim.x + threadIdx.x;
    if (idx >= N_NODES * 128) return;
    int d = idx & 127;
    int n = idx >> 7;
    float v;
    if (d < 96) {
        v = x[n * 96 + d];
    } else {
        int dd = d - 96;
        int which = dd >> 4;
        int c = dd & 15;
        v = pe_val(nlu[n * 2 + which], c);
    }
    g_h[idx] = v;
}

__global__ void build_ea_kernel(const float* __restrict__ eattr, const int* __restrict__ elu) {
    long long idx = (long long)blockIdx.x * blockDim.x + threadIdx.x;
    if (idx >= (long long)N_EDGES * 128) return;
    int d = (int)(idx & 127);
    int e = (int)(idx >> 7);
    float v;
    if (d < 96) {
        v = eattr[(size_t)e * 96 + d];
    } else {
        int dd = d - 96;
        int which = dd >> 4;
        int c = dd & 15;
        v = pe_val(elu[(size_t)e * 2 + which], c);
    }
    g_ea[idx] = v;
}

__global__ void zero_accum_kernel() {
    int idx = blockIdx.x * blockDim.x + threadIdx.x;
    if (idx < N_NODES * 128) g_numer[idx] = 0.0f;
    if (idx < N_NODES * 8)  g_denom[idx] = 0.0f;
}

// ---------------- node GEMM: q/k/v/skip = h @ W + b  (blockIdx.y selects which) ----------------
__global__ __launch_bounds__(256, 1)
void node_gemm_kernel(const float* __restrict__ Wq, const float* __restrict__ Wk,
                      const float* __restrict__ Wv, const float* __restrict__ Wsk,
                      const float* __restrict__ bq, const float* __restrict__ bk,
                      const float* __restrict__ bv, const float* __restrict__ bsk) {
    extern __shared__ float sm[];
    float* Bs = sm;            // 128x128 weight
    float* As = sm + 16384;    // 128x128 h tile
    int tid = threadIdx.x;
    int which = blockIdx.y;
    const float* W; const float* bias; float* out;
    switch (which) {
        case 0:  W = Wq;  bias = bq;  out = g_q;    break;
        case 1:  W = Wk;  bias = bk;  out = g_k;    break;
        case 2:  W = Wv;  bias = bv;  out = g_v;    break;
        default: W = Wsk; bias = bsk; out = g_skip; break;
    }
    int row0 = blockIdx.x * 128;

#pragma unroll
    for (int it = 0; it < 16; ++it) {
        int off = (it * 256 + tid) * 4;
        *(float4*)(Bs + off) = *(const float4*)(W + off);
        int r = row0 + (off >> 7);
        float4 a = make_float4(0.f, 0.f, 0.f, 0.f);
        if (r < N_NODES) a = *(const float4*)(g_h + (size_t)row0 * 128 + off);
        *(float4*)(As + off) = a;
    }
    __syncthreads();

    int tx = tid & 15, ty = tid >> 4;
    unsigned long long acc2[8][4];
#pragma unroll
    for (int i = 0; i < 8; ++i)
#pragma unroll
        for (int j = 0; j < 4; ++j) acc2[i][j] = 0ULL;

    const float* Asrow = As + (ty * 8) * 128;
#pragma unroll 4
    for (int k = 0; k < 128; ++k) {
        ulonglong2 bA = *(const ulonglong2*)(Bs + k * 128 + tx * 8);
        ulonglong2 bB = *(const ulonglong2*)(Bs + k * 128 + tx * 8 + 4);
#pragma unroll
        for (int i = 0; i < 8; ++i) {
            float a = Asrow[i * 128 + k];
            unsigned long long a2 = pack2(a, a);
            fma2(acc2[i][0], a2, bA.x);
            fma2(acc2[i][1], a2, bA.y);
            fma2(acc2[i][2], a2, bB.x);
            fma2(acc2[i][3], a2, bB.y);
        }
    }

    float4 c0 = *(const float4*)(bias + tx * 8);
    float4 c1 = *(const float4*)(bias + tx * 8 + 4);
#pragma unroll
    for (int i = 0; i < 8; ++i) {
        int r = row0 + ty * 8 + i;
        if (r < N_NODES) {
            float2 t0 = unpack2(acc2[i][0]), t1 = unpack2(acc2[i][1]);
            float2 t2 = unpack2(acc2[i][2]), t3 = unpack2(acc2[i][3]);
            float4 o0 = make_float4(t0.x + c0.x, t0.y + c0.y, t1.x + c0.z, t1.y + c0.w);
            float4 o1 = make_float4(t2.x + c1.x, t2.y + c1.y, t3.x + c1.z, t3.y + c1.w);
            *(float4*)(out + (size_t)r * 128 + tx * 8) = o0;
            *(float4*)(out + (size_t)r * 128 + tx * 8 + 4) = o1;
        }
    }
}

// ---------------- fused edge kernel: e=ea@We; alpha; p=exp(alpha); red denom & numer ----------------
__global__ __launch_bounds__(256, 1)
void edge_kernel(const float* __restrict__ We, const int* __restrict__ ei) {
    extern __shared__ float sm[];
    float* Bs = sm;            // We 128x128
    float* As = sm + 16384;    // ea tile 128x128
    int* s_src = (int*)(sm + 32768);
    int* s_dst = s_src + 128;
    int tid = threadIdx.x;
    int e0 = blockIdx.x << 7;

    if (tid < 128) {
        s_src[tid] = ei[e0 + tid];
        s_dst[tid] = ei[N_EDGES + e0 + tid];
    }
    const float* eaBase = g_ea + (size_t)e0 * 128;
#pragma unroll
    for (int it = 0; it < 16; ++it) {
        int off = (it * 256 + tid) * 4;
        *(float4*)(Bs + off) = *(const float4*)(We + off);
        *(float4*)(As + off) = *(const float4*)(eaBase + off);
    }
    __syncthreads();

    int tx = tid & 15, ty = tid >> 4;
    unsigned long long acc2[8][4];
#pragma unroll
    for (int i = 0; i < 8; ++i)
#pragma unroll
        for (int j = 0; j < 4; ++j) acc2[i][j] = 0ULL;

    const float* Asrow = As + (ty * 8) * 128;
#pragma unroll 4
    for (int k = 0; k < 128; ++k) {
        ulonglong2 bA = *(const ulonglong2*)(Bs + k * 128 + tx * 8);
        ulonglong2 bB = *(const ulonglong2*)(Bs + k * 128 + tx * 8 + 4);
#pragma unroll
        for (int i = 0; i < 8; ++i) {
            float a = Asrow[i * 128 + k];
            unsigned long long a2 = pack2(a, a);
            fma2(acc2[i][0], a2, bA.x);
            fma2(acc2[i][1], a2, bA.y);
            fma2(acc2[i][2], a2, bB.x);
            fma2(acc2[i][3], a2, bB.y);
        }
    }

    // alpha + softmax-numerator accumulation, all from registers (no e scratch).
    // Thread covers cols [tx*8, tx*8+8) = half of head hd = tx/2; pair (tx, tx^1)
    // are warp lanes (lane = (ty&1)*16 + tx), combined via shfl_xor(1).
    int hd = tx >> 1;
    int cb = tx << 3;
#pragma unroll
    for (int i = 0; i < 8; ++i) {
        float2 t0 = unpack2(acc2[i][0]), t1 = unpack2(acc2[i][1]);
        float2 t2 = unpack2(acc2[i][2]), t3 = unpack2(acc2[i][3]);
        float e8[8] = {t0.x, t0.y, t1.x, t1.y, t2.x, t2.y, t3.x, t3.y};
        int er = ty * 8 + i;
        int s = s_src[er], d = s_dst[er];
        const float* qp = g_q + (size_t)d * 128 + cb;
        const float* kp = g_k + (size_t)s * 128 + cb;
        float4 q0 = *(const float4*)qp, q1 = *(const float4*)(qp + 4);
        float4 k0 = *(const float4*)kp, k1 = *(const float4*)(kp + 4);
        float part = q0.x * (k0.x + e8[0]) + q0.y * (k0.y + e8[1])
                   + q0.z * (k0.z + e8[2]) + q0.w * (k0.w + e8[3])
                   + q1.x * (k1.x + e8[4]) + q1.y * (k1.y + e8[5])
                   + q1.z * (k1.z + e8[6]) + q1.w * (k1.w + e8[7]);
        float full = part + __shfl_xor_sync(0xffffffffu, part, 1);
        float p = expf(full * 0.25f);  // scale = 1/sqrt(16); shift-free softmax (alpha is O(1))
        if (!(tx & 1)) atomicAdd(g_denom + (size_t)d * 8 + hd, p);
        const float* vp = g_v + (size_t)s * 128 + cb;
        float4 v0 = *(const float4*)vp, v1 = *(const float4*)(vp + 4);
        float* np = g_numer + (size_t)d * 128 + cb;
        red_add4(np,     p * (v0.x + e8[0]), p * (v0.y + e8[1]), p * (v0.z + e8[2]), p * (v0.w + e8[3]));
        red_add4(np + 4, p * (v1.x + e8[4]), p * (v1.y + e8[5]), p * (v1.z + e8[6]), p * (v1.w + e8[7]));
    }
}

// ---------------- node update: h = relu(numer/(denom+eps) + skip) ----------------
__global__ void update_h_kernel() {
    int idx = blockIdx.x * blockDim.x + threadIdx.x;
    if (idx >= N_NODES * 128) return;
    int n = idx >> 7;
    int c = idx & 127;
    float den = g_denom[n * 8 + (c >> 4)];
    float v = g_numer[idx] / (den + 1e-16f) + g_skip[idx];
    g_h[idx] = fmaxf(v, 0.0f);
}

// ---------------- output GEMM: out = h @ Wout + bout  (128 -> 16) ----------------
__global__ void out_gemm_kernel(const float* __restrict__ Wout, const float* __restrict__ bout,
                                float* __restrict__ out) {
    __shared__ float ws[128 * 16];
    __shared__ float hs[16 * 128];
    int tid = threadIdx.x;
    int row0 = blockIdx.x * 16;
#pragma unroll
    for (int it = 0; it < 8; ++it) {
        int idx = it * 256 + tid;
        ws[idx] = Wout[idx];
        int r = row0 + (idx >> 7);
        hs[idx] = (r < N_NODES) ? g_h[(size_t)row0 * 128 + idx] : 0.0f;
    }
    __syncthreads();
    int r = tid >> 4, c = tid & 15;
    float s = bout[c];
#pragma unroll 8
    for (int k = 0; k < 128; ++k) s += hs[r * 128 + k] * ws[k * 16 + c];
    int gr = row0 + r;
    if (gr < N_NODES) out[(size_t)gr * 16 + c] = s;
}

// ---------------- host ----------------
extern "C" void kernel_launch(void* const* d_in, const int* in_sizes, int n_in,
                              void* d_out, int out_size) {
    const float* x     = (const float*)d_in[0];
    const int*   nlu   = (const int*)  d_in[1];
    const int*   ei    = (const int*)  d_in[2];
    const float* eattr = (const float*)d_in[3];
    const int*   elu   = (const int*)  d_in[4];
    const float* Wq    = (const float*)d_in[5];
    const float* bq    = (const float*)d_in[6];
    const float* Wk    = (const float*)d_in[7];
    const float* bk    = (const float*)d_in[8];
    const float* Wv    = (const float*)d_in[9];
    const float* bv    = (const float*)d_in[10];
    const float* We    = (const float*)d_in[11];
    const float* Ws    = (const float*)d_in[12];
    const float* bs    = (const float*)d_in[13];
    const float* Wout  = (const float*)d_in[14];
    const float* bout  = (const float*)d_in[15];
    float* out = (float*)d_out;

    (void)in_sizes; (void)n_in; (void)out_size;

    cudaFuncSetAttribute(node_gemm_kernel, cudaFuncAttributeMaxDynamicSharedMemorySize, 131072);
    cudaFuncSetAttribute(edge_kernel,      cudaFuncAttributeMaxDynamicSharedMemorySize, 132096);

    build_h_kernel <<<(N_NODES * 128 + 255) / 256, 256>>>(x, nlu);
    build_ea_kernel<<<(int)(((long long)N_EDGES * 128 + 255) / 256), 256>>>(eattr, elu);

    for (int l = 0; l < 3; ++l) {
        size_t wOff = (size_t)l * 128 * 128;
        size_t bOff = (size_t)l * 128;
        zero_accum_kernel<<<(N_NODES * 128 + 255) / 256, 256>>>();
        node_gemm_kernel<<<dim3((N_NODES + 127) / 128, 4), 256, 131072>>>(
            Wq + wOff, Wk + wOff, Wv + wOff, Ws + wOff,
            bq + bOff, bk + bOff, bv + bOff, bs + bOff);
        edge_kernel<<<N_EDGES / 128, 256, 132096>>>(We + wOff, ei);
        update_h_kernel<<<(N_NODES * 128 + 255) / 256, 256>>>();
    }
    out_gemm_kernel<<<N_NODES / 16, 256>>>(Wout, bout, out);
}

// round 3
// speedup vs baseline: 1.1359x; 1.1359x over previous
#include <cuda_runtime.h>
#include <math.h>

#define N_NODES 100000
#define N_EDGES 800000

// ---------------- device scratch ----------------
__device__ float g_h[(size_t)N_NODES * 128];
__device__ float g_ea[(size_t)N_EDGES * 128];    // edge features in DST-SORTED order
__device__ float g_q[(size_t)N_NODES * 128];
__device__ float g_k[(size_t)N_NODES * 128];
__device__ float g_v[(size_t)N_NODES * 128];
__device__ float g_skip[(size_t)N_NODES * 128];
__device__ float g_numer[(size_t)N_NODES * 128];
__device__ float g_denom[(size_t)N_NODES * 8];
// sort scratch
__device__ int g_count[N_NODES];
__device__ int g_off2[N_NODES];
__device__ int g_src_s[N_EDGES];
__device__ int g_dst_s[N_EDGES];
__device__ int g_perm[N_EDGES];

// ---------------- helpers ----------------
__device__ __forceinline__ void fma2(unsigned long long &d, unsigned long long a, unsigned long long b) {
    asm("fma.rn.f32x2 %0, %1, %2, %0;" : "+l"(d) : "l"(a), "l"(b));
}
__device__ __forceinline__ unsigned long long pack2(float lo, float hi) {
    unsigned long long r;
    asm("mov.b64 %0, {%1, %2};" : "=l"(r) : "f"(lo), "f"(hi));
    return r;
}
__device__ __forceinline__ float2 unpack2(unsigned long long v) {
    float lo, hi;
    asm("mov.b64 {%0, %1}, %2;" : "=f"(lo), "=f"(hi) : "l"(v));
    return make_float2(lo, hi);
}
__device__ __forceinline__ void red_add4(float* addr, float a, float b, float c, float d) {
    asm volatile("red.global.add.v4.f32 [%0], {%1, %2, %3, %4};"
                 :: "l"(addr), "f"(a), "f"(b), "f"(c), "f"(d) : "memory");
}
__device__ __forceinline__ float pe_val(int t, int c) {
    int j = c >> 1;
    float freq = expf(-logf(10000.0f) * (float)(2 * j) * (1.0f / 16.0f));
    float ang = (float)t * freq;
    return (c & 1) ? cosf(ang) : sinf(ang);
}

// ---------------- sort-by-dst (counting sort) ----------------
__global__ void zero_count_kernel() {
    int i = blockIdx.x * blockDim.x + threadIdx.x;
    if (i < N_NODES) g_count[i] = 0;
}
__global__ void hist_kernel(const int* __restrict__ ei) {
    int e = blockIdx.x * blockDim.x + threadIdx.x;
    if (e < N_EDGES) atomicAdd(&g_count[ei[N_EDGES + e]], 1);
}
__global__ void scan_kernel() {   // single block, 1024 threads: exclusive scan -> g_off2
    __shared__ int warp_sums[32];
    __shared__ int s_carry;
    int tid = threadIdx.x;
    int lane = tid & 31, wid = tid >> 5;
    if (tid == 0) s_carry = 0;
    __syncthreads();
    for (int base = 0; base < N_NODES; base += 1024) {
        int idx = base + tid;
        int v = (idx < N_NODES) ? g_count[idx] : 0;
        int inc = v;
#pragma unroll
        for (int o = 1; o < 32; o <<= 1) {
            int t = __shfl_up_sync(0xffffffffu, inc, o);
            if (lane >= o) inc += t;
        }
        if (lane == 31) warp_sums[wid] = inc;
        __syncthreads();
        if (wid == 0) {
            int w = warp_sums[lane];
            int wi = w;
#pragma unroll
            for (int o = 1; o < 32; o <<= 1) {
                int t = __shfl_up_sync(0xffffffffu, wi, o);
                if (lane >= o) wi += t;
            }
            warp_sums[lane] = wi - w;
        }
        __syncthreads();
        int ex = inc - v + warp_sums[wid] + s_carry;
        if (idx < N_NODES) g_off2[idx] = ex;
        __syncthreads();
        if (tid == 1023) s_carry = ex + v;
        __syncthreads();
    }
}
__global__ void scatter_kernel(const int* __restrict__ ei) {
    int e = blockIdx.x * blockDim.x + threadIdx.x;
    if (e >= N_EDGES) return;
    int d = ei[N_EDGES + e];
    int pos = atomicAdd(&g_off2[d], 1);
    g_src_s[pos] = ei[e];
    g_dst_s[pos] = d;
    g_perm[pos] = e;
}

// ---------------- builders ----------------
__global__ void build_h_kernel(const float* __restrict__ x, const int* __restrict__ nlu) {
    int idx = blockIdx.x * blockDim.x + threadIdx.x;
    if (idx >= N_NODES * 128) return;
    int d = idx & 127;
    int n = idx >> 7;
    float v;
    if (d < 96) v = x[n * 96 + d];
    else {
        int dd = d - 96;
        v = pe_val(nlu[n * 2 + (dd >> 4)], dd & 15);
    }
    g_h[idx] = v;
}
// builds ea directly in SORTED edge order
__global__ void build_ea_kernel(const float* __restrict__ eattr, const int* __restrict__ elu) {
    long long idx = (long long)blockIdx.x * blockDim.x + threadIdx.x;
    if (idx >= (long long)N_EDGES * 128) return;
    int d = (int)(idx & 127);
    int p = (int)(idx >> 7);
    int e = g_perm[p];
    float v;
    if (d < 96) v = eattr[(size_t)e * 96 + d];
    else {
        int dd = d - 96;
        v = pe_val(elu[(size_t)e * 2 + (dd >> 4)], dd & 15);
    }
    g_ea[idx] = v;
}
__global__ void zero_accum_kernel() {
    int idx = blockIdx.x * blockDim.x + threadIdx.x;
    if (idx < N_NODES * 128) g_numer[idx] = 0.0f;
    if (idx < N_NODES * 8)  g_denom[idx] = 0.0f;
}

// ---------------- node GEMM ----------------
__global__ __launch_bounds__(256, 1)
void node_gemm_kernel(const float* __restrict__ Wq, const float* __restrict__ Wk,
                      const float* __restrict__ Wv, const float* __restrict__ Wsk,
                      const float* __restrict__ bq, const float* __restrict__ bk,
                      const float* __restrict__ bv, const float* __restrict__ bsk) {
    extern __shared__ float sm[];
    float* Bs = sm;
    float* As = sm + 16384;
    int tid = threadIdx.x;
    int which = blockIdx.y;
    const float* W; const float* bias; float* out;
    switch (which) {
        case 0:  W = Wq;  bias = bq;  out = g_q;    break;
        case 1:  W = Wk;  bias = bk;  out = g_k;    break;
        case 2:  W = Wv;  bias = bv;  out = g_v;    break;
        default: W = Wsk; bias = bsk; out = g_skip; break;
    }
    int row0 = blockIdx.x * 128;

#pragma unroll
    for (int it = 0; it < 16; ++it) {
        int off = (it * 256 + tid) * 4;
        *(float4*)(Bs + off) = *(const float4*)(W + off);
        int r = row0 + (off >> 7);
        float4 a = make_float4(0.f, 0.f, 0.f, 0.f);
        if (r < N_NODES) a = *(const float4*)(g_h + (size_t)row0 * 128 + off);
        *(float4*)(As + off) = a;
    }
    __syncthreads();

    int tx = tid & 15, ty = tid >> 4;
    unsigned long long acc2[8][4];
#pragma unroll
    for (int i = 0; i < 8; ++i)
#pragma unroll
        for (int j = 0; j < 4; ++j) acc2[i][j] = 0ULL;

    const float* Asrow = As + (ty * 8) * 128;
#pragma unroll 2
    for (int k4 = 0; k4 < 128; k4 += 4) {
        float4 a4[8];
#pragma unroll
        for (int i = 0; i < 8; ++i) a4[i] = *(const float4*)(Asrow + i * 128 + k4);
#pragma unroll
        for (int j = 0; j < 4; ++j) {
            int k = k4 + j;
            ulonglong2 bA = *(const ulonglong2*)(Bs + k * 128 + tx * 8);
            ulonglong2 bB = *(const ulonglong2*)(Bs + k * 128 + tx * 8 + 4);
#pragma unroll
            for (int i = 0; i < 8; ++i) {
                float a = (j == 0) ? a4[i].x : (j == 1) ? a4[i].y : (j == 2) ? a4[i].z : a4[i].w;
                unsigned long long a2 = pack2(a, a);
                fma2(acc2[i][0], a2, bA.x);
                fma2(acc2[i][1], a2, bA.y);
                fma2(acc2[i][2], a2, bB.x);
                fma2(acc2[i][3], a2, bB.y);
            }
        }
    }

    float4 c0 = *(const float4*)(bias + tx * 8);
    float4 c1 = *(const float4*)(bias + tx * 8 + 4);
#pragma unroll
    for (int i = 0; i < 8; ++i) {
        int r = row0 + ty * 8 + i;
        if (r < N_NODES) {
            float2 t0 = unpack2(acc2[i][0]), t1 = unpack2(acc2[i][1]);
            float2 t2 = unpack2(acc2[i][2]), t3 = unpack2(acc2[i][3]);
            float4 o0 = make_float4(t0.x + c0.x, t0.y + c0.y, t1.x + c0.z, t1.y + c0.w);
            float4 o1 = make_float4(t2.x + c1.x, t2.y + c1.y, t3.x + c1.z, t3.y + c1.w);
            *(float4*)(out + (size_t)r * 128 + tx * 8) = o0;
            *(float4*)(out + (size_t)r * 128 + tx * 8 + 4) = o1;
        }
    }
}

// ---------------- fused edge kernel (dst-sorted, run-coalesced atomics) ----------------
__global__ __launch_bounds__(256, 1)
void edge_kernel(const float* __restrict__ We) {
    extern __shared__ float sm[];
    float* Bs = sm;
    float* As = sm + 16384;
    int* s_src = (int*)(sm + 32768);
    int* s_dst = s_src + 128;
    int tid = threadIdx.x;
    int e0 = blockIdx.x << 7;

    if (tid < 128) {
        s_src[tid] = g_src_s[e0 + tid];
        s_dst[tid] = g_dst_s[e0 + tid];
    }
    const float* eaBase = g_ea + (size_t)e0 * 128;
#pragma unroll
    for (int it = 0; it < 16; ++it) {
        int off = (it * 256 + tid) * 4;
        *(float4*)(Bs + off) = *(const float4*)(We + off);
        *(float4*)(As + off) = *(const float4*)(eaBase + off);
    }
    __syncthreads();

    int tx = tid & 15, ty = tid >> 4;
    unsigned long long acc2[8][4];
#pragma unroll
    for (int i = 0; i < 8; ++i)
#pragma unroll
        for (int j = 0; j < 4; ++j) acc2[i][j] = 0ULL;

    const float* Asrow = As + (ty * 8) * 128;
#pragma unroll 2
    for (int k4 = 0; k4 < 128; k4 += 4) {
        float4 a4[8];
#pragma unroll
        for (int i = 0; i < 8; ++i) a4[i] = *(const float4*)(Asrow + i * 128 + k4);
#pragma unroll
        for (int j = 0; j < 4; ++j) {
            int k = k4 + j;
            ulonglong2 bA = *(const ulonglong2*)(Bs + k * 128 + tx * 8);
            ulonglong2 bB = *(const ulonglong2*)(Bs + k * 128 + tx * 8 + 4);
#pragma unroll
            for (int i = 0; i < 8; ++i) {
                float a = (j == 0) ? a4[i].x : (j == 1) ? a4[i].y : (j == 2) ? a4[i].z : a4[i].w;
                unsigned long long a2 = pack2(a, a);
                fma2(acc2[i][0], a2, bA.x);
                fma2(acc2[i][1], a2, bA.y);
                fma2(acc2[i][2], a2, bB.x);
                fma2(acc2[i][3], a2, bB.y);
            }
        }
    }

    // Epilogue: edges in this tile are dst-sorted -> accumulate runs in registers,
    // flush one red.v4 pair per distinct dst per thread.
    int hd = tx >> 1;
    int cb = tx << 3;
    int cur_d = -1;
    float aN0 = 0.f, aN1 = 0.f, aN2 = 0.f, aN3 = 0.f;
    float aN4 = 0.f, aN5 = 0.f, aN6 = 0.f, aN7 = 0.f;
    float aD = 0.f;
#pragma unroll
    for (int i = 0; i < 8; ++i) {
        float2 t0 = unpack2(acc2[i][0]), t1 = unpack2(acc2[i][1]);
        float2 t2 = unpack2(acc2[i][2]), t3 = unpack2(acc2[i][3]);
        float e8[8] = {t0.x, t0.y, t1.x, t1.y, t2.x, t2.y, t3.x, t3.y};
        int er = ty * 8 + i;
        int s = s_src[er], d = s_dst[er];
        const float* qp = g_q + (size_t)d * 128 + cb;
        const float* kp = g_k + (size_t)s * 128 + cb;
        float4 q0 = *(const float4*)qp, q1 = *(const float4*)(qp + 4);
        float4 k0 = *(const float4*)kp, k1 = *(const float4*)(kp + 4);
        float part = q0.x * (k0.x + e8[0]) + q0.y * (k0.y + e8[1])
                   + q0.z * (k0.z + e8[2]) + q0.w * (k0.w + e8[3])
                   + q1.x * (k1.x + e8[4]) + q1.y * (k1.y + e8[5])
                   + q1.z * (k1.z + e8[6]) + q1.w * (k1.w + e8[7]);
        float full = part + __shfl_xor_sync(0xffffffffu, part, 1);
        float p = expf(full * 0.25f);  // shift-free softmax (alpha is O(1))
        if (d != cur_d) {
            if (cur_d >= 0) {
                float* np = g_numer + (size_t)cur_d * 128 + cb;
                red_add4(np,     aN0, aN1, aN2, aN3);
                red_add4(np + 4, aN4, aN5, aN6, aN7);
                if (!(tx & 1)) atomicAdd(g_denom + (size_t)cur_d * 8 + hd, aD);
            }
            cur_d = d;
            aN0 = aN1 = aN2 = aN3 = aN4 = aN5 = aN6 = aN7 = 0.f;
            aD = 0.f;
        }
        const float* vp = g_v + (size_t)s * 128 + cb;
        float4 v0 = *(const float4*)vp, v1 = *(const float4*)(vp + 4);
        aN0 += p * (v0.x + e8[0]); aN1 += p * (v0.y + e8[1]);
        aN2 += p * (v0.z + e8[2]); aN3 += p * (v0.w + e8[3]);
        aN4 += p * (v1.x + e8[4]); aN5 += p * (v1.y + e8[5]);
        aN6 += p * (v1.z + e8[6]); aN7 += p * (v1.w + e8[7]);
        aD += p;
    }
    {
        float* np = g_numer + (size_t)cur_d * 128 + cb;
        red_add4(np,     aN0, aN1, aN2, aN3);
        red_add4(np + 4, aN4, aN5, aN6, aN7);
        if (!(tx & 1)) atomicAdd(g_denom + (size_t)cur_d * 8 + hd, aD);
    }
}

// ---------------- node update ----------------
__global__ void update_h_kernel() {
    int idx = blockIdx.x * blockDim.x + threadIdx.x;
    if (idx >= N_NODES * 128) return;
    int n = idx >> 7;
    int c = idx & 127;
    float den = g_denom[n * 8 + (c >> 4)];
    float v = g_numer[idx] / (den + 1e-16f) + g_skip[idx];
    g_h[idx] = fmaxf(v, 0.0f);
}

// ---------------- output GEMM ----------------
__global__ void out_gemm_kernel(const float* __restrict__ Wout, const float* __restrict__ bout,
                                float* __restrict__ out) {
    __shared__ float ws[128 * 16];
    __shared__ float hs[16 * 128];
    int tid = threadIdx.x;
    int row0 = blockIdx.x * 16;
#pragma unroll
    for (int it = 0; it < 8; ++it) {
        int idx = it * 256 + tid;
        ws[idx] = Wout[idx];
        int r = row0 + (idx >> 7);
        hs[idx] = (r < N_NODES) ? g_h[(size_t)row0 * 128 + idx] : 0.0f;
    }
    __syncthreads();
    int r = tid >> 4, c = tid & 15;
    float s = bout[c];
#pragma unroll 8
    for (int k = 0; k < 128; ++k) s += hs[r * 128 + k] * ws[k * 16 + c];
    int gr = row0 + r;
    if (gr < N_NODES) out[(size_t)gr * 16 + c] = s;
}

// ---------------- host ----------------
extern "C" void kernel_launch(void* const* d_in, const int* in_sizes, int n_in,
                              void* d_out, int out_size) {
    const float* x     = (const float*)d_in[0];
    const int*   nlu   = (const int*)  d_in[1];
    const int*   ei    = (const int*)  d_in[2];
    const float* eattr = (const float*)d_in[3];
    const int*   elu   = (const int*)  d_in[4];
    const float* Wq    = (const float*)d_in[5];
    const float* bq    = (const float*)d_in[6];
    const float* Wk    = (const float*)d_in[7];
    const float* bk    = (const float*)d_in[8];
    const float* Wv    = (const float*)d_in[9];
    const float* bv    = (const float*)d_in[10];
    const float* We    = (const float*)d_in[11];
    const float* Ws    = (const float*)d_in[12];
    const float* bs    = (const float*)d_in[13];
    const float* Wout  = (const float*)d_in[14];
    const float* bout  = (const float*)d_in[15];
    float* out = (float*)d_out;

    (void)in_sizes; (void)n_in; (void)out_size;

    cudaFuncSetAttribute(node_gemm_kernel, cudaFuncAttributeMaxDynamicSharedMemorySize, 131072);
    cudaFuncSetAttribute(edge_kernel,      cudaFuncAttributeMaxDynamicSharedMemorySize, 132096);

    // sort edges by dst
    zero_count_kernel<<<(N_NODES + 255) / 256, 256>>>();
    hist_kernel<<<(N_EDGES + 255) / 256, 256>>>(ei);
    scan_kernel<<<1, 1024>>>();
    scatter_kernel<<<(N_EDGES + 255) / 256, 256>>>(ei);

    build_h_kernel <<<(N_NODES * 128 + 255) / 256, 256>>>(x, nlu);
    build_ea_kernel<<<(int)(((long long)N_EDGES * 128 + 255) / 256), 256>>>(eattr, elu);

    for (int l = 0; l < 3; ++l) {
        size_t wOff = (size_t)l * 128 * 128;
        size_t bOff = (size_t)l * 128;
        zero_accum_kernel<<<(N_NODES * 128 + 255) / 256, 256>>>();
        node_gemm_kernel<<<dim3((N_NODES + 127) / 128, 4), 256, 131072>>>(
            Wq + wOff, Wk + wOff, Wv + wOff, Ws + wOff,
            bq + bOff, bk + bOff, bv + bOff, bs + bOff);
        edge_kernel<<<N_EDGES / 128, 256, 132096>>>(We + wOff);
        update_h_kernel<<<(N_NODES * 128 + 255) / 256, 256>>>();
    }
    out_gemm_kernel<<<N_NODES / 16, 256>>>(Wout, bout, out);
}

// round 4
// speedup vs baseline: 1.1370x; 1.0010x over previous
#include <cuda_runtime.h>
#include <math.h>

#define N_NODES 100000
#define N_EDGES 800000

// ---------------- device scratch ----------------
__device__ float g_h[(size_t)N_NODES * 128];
__device__ float g_ea[(size_t)N_EDGES * 128];    // edge features in DST-SORTED order
__device__ float g_q[(size_t)N_NODES * 128];
__device__ float g_k[(size_t)N_NODES * 128];
__device__ float g_v[(size_t)N_NODES * 128];
__device__ float g_skip[(size_t)N_NODES * 128];
__device__ float g_numer[(size_t)N_NODES * 128];
__device__ float g_denom[(size_t)N_NODES * 8];
// sort scratch
__device__ int g_count[N_NODES];
__device__ int g_off2[N_NODES];
__device__ int g_src_s[N_EDGES];
__device__ int g_dst_s[N_EDGES];
__device__ int g_perm[N_EDGES];

// ---------------- helpers ----------------
__device__ __forceinline__ void fma2(unsigned long long &d, unsigned long long a, unsigned long long b) {
    asm("fma.rn.f32x2 %0, %1, %2, %0;" : "+l"(d) : "l"(a), "l"(b));
}
__device__ __forceinline__ unsigned long long pack2(float lo, float hi) {
    unsigned long long r;
    asm("mov.b64 %0, {%1, %2};" : "=l"(r) : "f"(lo), "f"(hi));
    return r;
}
__device__ __forceinline__ float2 unpack2(unsigned long long v) {
    float lo, hi;
    asm("mov.b64 {%0, %1}, %2;" : "=f"(lo), "=f"(hi) : "l"(v));
    return make_float2(lo, hi);
}
__device__ __forceinline__ void red_add4(float* addr, float a, float b, float c, float d) {
    asm volatile("red.global.add.v4.f32 [%0], {%1, %2, %3, %4};"
                 :: "l"(addr), "f"(a), "f"(b), "f"(c), "f"(d) : "memory");
}
__device__ __forceinline__ float pe_val(int t, int c) {
    int j = c >> 1;
    float freq = expf(-logf(10000.0f) * (float)(2 * j) * (1.0f / 16.0f));
    float ang = (float)t * freq;
    return (c & 1) ? cosf(ang) : sinf(ang);
}

// ---------------- sort-by-dst (counting sort) ----------------
__global__ void zero_count_kernel() {
    int i = blockIdx.x * blockDim.x + threadIdx.x;
    if (i < N_NODES) g_count[i] = 0;
}
__global__ void hist_kernel(const int* __restrict__ ei) {
    int e = blockIdx.x * blockDim.x + threadIdx.x;
    if (e < N_EDGES) atomicAdd(&g_count[ei[N_EDGES + e]], 1);
}
__global__ void scan_kernel() {   // single block, 1024 threads: exclusive scan -> g_off2
    __shared__ int warp_sums[32];
    __shared__ int s_carry;
    int tid = threadIdx.x;
    int lane = tid & 31, wid = tid >> 5;
    if (tid == 0) s_carry = 0;
    __syncthreads();
    for (int base = 0; base < N_NODES; base += 1024) {
        int idx = base + tid;
        int v = (idx < N_NODES) ? g_count[idx] : 0;
        int inc = v;
#pragma unroll
        for (int o = 1; o < 32; o <<= 1) {
            int t = __shfl_up_sync(0xffffffffu, inc, o);
            if (lane >= o) inc += t;
        }
        if (lane == 31) warp_sums[wid] = inc;
        __syncthreads();
        if (wid == 0) {
            int w = warp_sums[lane];
            int wi = w;
#pragma unroll
            for (int o = 1; o < 32; o <<= 1) {
                int t = __shfl_up_sync(0xffffffffu, wi, o);
                if (lane >= o) wi += t;
            }
            warp_sums[lane] = wi - w;
        }
        __syncthreads();
        int ex = inc - v + warp_sums[wid] + s_carry;
        if (idx < N_NODES) g_off2[idx] = ex;
        __syncthreads();
        if (tid == 1023) s_carry = ex + v;
        __syncthreads();
    }
}
__global__ void scatter_kernel(const int* __restrict__ ei) {
    int e = blockIdx.x * blockDim.x + threadIdx.x;
    if (e >= N_EDGES) return;
    int d = ei[N_EDGES + e];
    int pos = atomicAdd(&g_off2[d], 1);
    g_src_s[pos] = ei[e];
    g_dst_s[pos] = d;
    g_perm[pos] = e;
}

// ---------------- builders ----------------
__global__ void build_h_kernel(const float* __restrict__ x, const int* __restrict__ nlu) {
    int idx = blockIdx.x * blockDim.x + threadIdx.x;
    if (idx >= N_NODES * 128) return;
    int d = idx & 127;
    int n = idx >> 7;
    float v;
    if (d < 96) v = x[n * 96 + d];
    else {
        int dd = d - 96;
        v = pe_val(nlu[n * 2 + (dd >> 4)], dd & 15);
    }
    g_h[idx] = v;
}
// builds ea directly in SORTED edge order
__global__ void build_ea_kernel(const float* __restrict__ eattr, const int* __restrict__ elu) {
    long long idx = (long long)blockIdx.x * blockDim.x + threadIdx.x;
    if (idx >= (long long)N_EDGES * 128) return;
    int d = (int)(idx & 127);
    int p = (int)(idx >> 7);
    int e = g_perm[p];
    float v;
    if (d < 96) v = eattr[(size_t)e * 96 + d];
    else {
        int dd = d - 96;
        v = pe_val(elu[(size_t)e * 2 + (dd >> 4)], dd & 15);
    }
    g_ea[idx] = v;
}
__global__ void zero_accum_kernel() {
    int idx = blockIdx.x * blockDim.x + threadIdx.x;
    if (idx < N_NODES * 128) g_numer[idx] = 0.0f;
    if (idx < N_NODES * 8)  g_denom[idx] = 0.0f;
}

// ---------------- node GEMM ----------------
__global__ __launch_bounds__(256, 1)
void node_gemm_kernel(const float* __restrict__ Wq, const float* __restrict__ Wk,
                      const float* __restrict__ Wv, const float* __restrict__ Wsk,
                      const float* __restrict__ bq, const float* __restrict__ bk,
                      const float* __restrict__ bv, const float* __restrict__ bsk) {
    extern __shared__ float sm[];
    float* Bs = sm;
    float* As = sm + 16384;
    int tid = threadIdx.x;
    int which = blockIdx.y;
    const float* W; const float* bias; float* out;
    switch (which) {
        case 0:  W = Wq;  bias = bq;  out = g_q;    break;
        case 1:  W = Wk;  bias = bk;  out = g_k;    break;
        case 2:  W = Wv;  bias = bv;  out = g_v;    break;
        default: W = Wsk; bias = bsk; out = g_skip; break;
    }
    int row0 = blockIdx.x * 128;

#pragma unroll
    for (int it = 0; it < 16; ++it) {
        int off = (it * 256 + tid) * 4;
        *(float4*)(Bs + off) = *(const float4*)(W + off);
        int r = row0 + (off >> 7);
        float4 a = make_float4(0.f, 0.f, 0.f, 0.f);
        if (r < N_NODES) a = *(const float4*)(g_h + (size_t)row0 * 128 + off);
        *(float4*)(As + off) = a;
    }
    __syncthreads();

    int tx = tid & 15, ty = tid >> 4;
    unsigned long long acc2[8][4];
#pragma unroll
    for (int i = 0; i < 8; ++i)
#pragma unroll
        for (int j = 0; j < 4; ++j) acc2[i][j] = 0ULL;

    const float* Asrow = As + (ty * 8) * 128;
#pragma unroll 2
    for (int k4 = 0; k4 < 128; k4 += 4) {
        float4 a4[8];
#pragma unroll
        for (int i = 0; i < 8; ++i) a4[i] = *(const float4*)(Asrow + i * 128 + k4);
#pragma unroll
        for (int j = 0; j < 4; ++j) {
            int k = k4 + j;
            ulonglong2 bA = *(const ulonglong2*)(Bs + k * 128 + tx * 8);
            ulonglong2 bB = *(const ulonglong2*)(Bs + k * 128 + tx * 8 + 4);
#pragma unroll
            for (int i = 0; i < 8; ++i) {
                float a = (j == 0) ? a4[i].x : (j == 1) ? a4[i].y : (j == 2) ? a4[i].z : a4[i].w;
                unsigned long long a2 = pack2(a, a);
                fma2(acc2[i][0], a2, bA.x);
                fma2(acc2[i][1], a2, bA.y);
                fma2(acc2[i][2], a2, bB.x);
                fma2(acc2[i][3], a2, bB.y);
            }
        }
    }

    float4 c0 = *(const float4*)(bias + tx * 8);
    float4 c1 = *(const float4*)(bias + tx * 8 + 4);
#pragma unroll
    for (int i = 0; i < 8; ++i) {
        int r = row0 + ty * 8 + i;
        if (r < N_NODES) {
            float2 t0 = unpack2(acc2[i][0]), t1 = unpack2(acc2[i][1]);
            float2 t2 = unpack2(acc2[i][2]), t3 = unpack2(acc2[i][3]);
            float4 o0 = make_float4(t0.x + c0.x, t0.y + c0.y, t1.x + c0.z, t1.y + c0.w);
            float4 o1 = make_float4(t2.x + c1.x, t2.y + c1.y, t3.x + c1.z, t3.y + c1.w);
            *(float4*)(out + (size_t)r * 128 + tx * 8) = o0;
            *(float4*)(out + (size_t)r * 128 + tx * 8 + 4) = o1;
        }
    }
}

// ---------------- fused edge kernel (dst-sorted, run-coalesced atomics) ----------------
__global__ __launch_bounds__(256, 1)
void edge_kernel(const float* __restrict__ We) {
    extern __shared__ float sm[];
    float* Bs = sm;
    float* As = sm + 16384;
    int* s_src = (int*)(sm + 32768);
    int* s_dst = s_src + 128;
    int tid = threadIdx.x;
    int e0 = blockIdx.x << 7;

    if (tid < 128) {
        s_src[tid] = g_src_s[e0 + tid];
        s_dst[tid] = g_dst_s[e0 + tid];
    }
    const float* eaBase = g_ea + (size_t)e0 * 128;
#pragma unroll
    for (int it = 0; it < 16; ++it) {
        int off = (it * 256 + tid) * 4;
        *(float4*)(Bs + off) = *(const float4*)(We + off);
        *(float4*)(As + off) = *(const float4*)(eaBase + off);
    }
    __syncthreads();

    int tx = tid & 15, ty = tid >> 4;
    unsigned long long acc2[8][4];
#pragma unroll
    for (int i = 0; i < 8; ++i)
#pragma unroll
        for (int j = 0; j < 4; ++j) acc2[i][j] = 0ULL;

    const float* Asrow = As + (ty * 8) * 128;
#pragma unroll 2
    for (int k4 = 0; k4 < 128; k4 += 4) {
        float4 a4[8];
#pragma unroll
        for (int i = 0; i < 8; ++i) a4[i] = *(const float4*)(Asrow + i * 128 + k4);
#pragma unroll
        for (int j = 0; j < 4; ++j) {
            int k = k4 + j;
            ulonglong2 bA = *(const ulonglong2*)(Bs + k * 128 + tx * 8);
            ulonglong2 bB = *(const ulonglong2*)(Bs + k * 128 + tx * 8 + 4);
#pragma unroll
            for (int i = 0; i < 8; ++i) {
                float a = (j == 0) ? a4[i].x : (j == 1) ? a4[i].y : (j == 2) ? a4[i].z : a4[i].w;
                unsigned long long a2 = pack2(a, a);
                fma2(acc2[i][0], a2, bA.x);
                fma2(acc2[i][1], a2, bA.y);
                fma2(acc2[i][2], a2, bB.x);
                fma2(acc2[i][3], a2, bB.y);
            }
        }
    }

    // Epilogue: edges in this tile are dst-sorted -> accumulate runs in registers,
    // flush one red.v4 pair per distinct dst per thread.
    int hd = tx >> 1;
    int cb = tx << 3;
    int cur_d = -1;
    float aN0 = 0.f, aN1 = 0.f, aN2 = 0.f, aN3 = 0.f;
    float aN4 = 0.f, aN5 = 0.f, aN6 = 0.f, aN7 = 0.f;
    float aD = 0.f;
#pragma unroll
    for (int i = 0; i < 8; ++i) {
        float2 t0 = unpack2(acc2[i][0]), t1 = unpack2(acc2[i][1]);
        float2 t2 = unpack2(acc2[i][2]), t3 = unpack2(acc2[i][3]);
        float e8[8] = {t0.x, t0.y, t1.x, t1.y, t2.x, t2.y, t3.x, t3.y};
        int er = ty * 8 + i;
        int s = s_src[er], d = s_dst[er];
        const float* qp = g_q + (size_t)d * 128 + cb;
        const float* kp = g_k + (size_t)s * 128 + cb;
        float4 q0 = *(const float4*)qp, q1 = *(const float4*)(qp + 4);
        float4 k0 = *(const float4*)kp, k1 = *(const float4*)(kp + 4);
        float part = q0.x * (k0.x + e8[0]) + q0.y * (k0.y + e8[1])
                   + q0.z * (k0.z + e8[2]) + q0.w * (k0.w + e8[3])
                   + q1.x * (k1.x + e8[4]) + q1.y * (k1.y + e8[5])
                   + q1.z * (k1.z + e8[6]) + q1.w * (k1.w + e8[7]);
        float full = part + __shfl_xor_sync(0xffffffffu, part, 1);
        float p = expf(full * 0.25f);  // shift-free softmax (alpha is O(1))
        if (d != cur_d) {
            if (cur_d >= 0) {
                float* np = g_numer + (size_t)cur_d * 128 + cb;
                red_add4(np,     aN0, aN1, aN2, aN3);
                red_add4(np + 4, aN4, aN5, aN6, aN7);
                if (!(tx & 1)) atomicAdd(g_denom + (size_t)cur_d * 8 + hd, aD);
            }
            cur_d = d;
            aN0 = aN1 = aN2 = aN3 = aN4 = aN5 = aN6 = aN7 = 0.f;
            aD = 0.f;
        }
        const float* vp = g_v + (size_t)s * 128 + cb;
        float4 v0 = *(const float4*)vp, v1 = *(const float4*)(vp + 4);
        aN0 += p * (v0.x + e8[0]); aN1 += p * (v0.y + e8[1]);
        aN2 += p * (v0.z + e8[2]); aN3 += p * (v0.w + e8[3]);
        aN4 += p * (v1.x + e8[4]); aN5 += p * (v1.y + e8[5]);
        aN6 += p * (v1.z + e8[6]); aN7 += p * (v1.w + e8[7]);
        aD += p;
    }
    {
        float* np = g_numer + (size_t)cur_d * 128 + cb;
        red_add4(np,     aN0, aN1, aN2, aN3);
        red_add4(np + 4, aN4, aN5, aN6, aN7);
        if (!(tx & 1)) atomicAdd(g_denom + (size_t)cur_d * 8 + hd, aD);
    }
}

// ---------------- node update ----------------
__global__ void update_h_kernel() {
    int idx = blockIdx.x * blockDim.x + threadIdx.x;
    if (idx >= N_NODES * 128) return;
    int n = idx >> 7;
    int c = idx & 127;
    float den = g_denom[n * 8 + (c >> 4)];
    float v = g_numer[idx] / (den + 1e-16f) + g_skip[idx];
    g_h[idx] = fmaxf(v, 0.0f);
}

// ---------------- output GEMM ----------------
__global__ void out_gemm_kernel(const float* __restrict__ Wout, const float* __restrict__ bout,
                                float* __restrict__ out) {
    __shared__ float ws[128 * 16];
    __shared__ float hs[16 * 128];
    int tid = threadIdx.x;
    int row0 = blockIdx.x * 16;
#pragma unroll
    for (int it = 0; it < 8; ++it) {
        int idx = it * 256 + tid;
        ws[idx] = Wout[idx];
        int r = row0 + (idx >> 7);
        hs[idx] = (r < N_NODES) ? g_h[(size_t)row0 * 128 + idx] : 0.0f;
    }
    __syncthreads();
    int r = tid >> 4, c = tid & 15;
    float s = bout[c];
#pragma unroll 8
    for (int k = 0; k < 128; ++k) s += hs[r * 128 + k] * ws[k * 16 + c];
    int gr = row0 + r;
    if (gr < N_NODES) out[(size_t)gr * 16 + c] = s;
}

// ---------------- host ----------------
extern "C" void kernel_launch(void* const* d_in, const int* in_sizes, int n_in,
                              void* d_out, int out_size) {
    const float* x     = (const float*)d_in[0];
    const int*   nlu   = (const int*)  d_in[1];
    const int*   ei    = (const int*)  d_in[2];
    const float* eattr = (const float*)d_in[3];
    const int*   elu   = (const int*)  d_in[4];
    const float* Wq    = (const float*)d_in[5];
    const float* bq    = (const float*)d_in[6];
    const float* Wk    = (const float*)d_in[7];
    const float* bk    = (const float*)d_in[8];
    const float* Wv    = (const float*)d_in[9];
    const float* bv    = (const float*)d_in[10];
    const float* We    = (const float*)d_in[11];
    const float* Ws    = (const float*)d_in[12];
    const float* bs    = (const float*)d_in[13];
    const float* Wout  = (const float*)d_in[14];
    const float* bout  = (const float*)d_in[15];
    float* out = (float*)d_out;

    (void)in_sizes; (void)n_in; (void)out_size;

    cudaFuncSetAttribute(node_gemm_kernel, cudaFuncAttributeMaxDynamicSharedMemorySize, 131072);
    cudaFuncSetAttribute(edge_kernel,      cudaFuncAttributeMaxDynamicSharedMemorySize, 132096);

    // sort edges by dst
    zero_count_kernel<<<(N_NODES + 255) / 256, 256>>>();
    hist_kernel<<<(N_EDGES + 255) / 256, 256>>>(ei);
    scan_kernel<<<1, 1024>>>();
    scatter_kernel<<<(N_EDGES + 255) / 256, 256>>>(ei);

    build_h_kernel <<<(N_NODES * 128 + 255) / 256, 256>>>(x, nlu);
    build_ea_kernel<<<(int)(((long long)N_EDGES * 128 + 255) / 256), 256>>>(eattr, elu);

    for (int l = 0; l < 3; ++l) {
        size_t wOff = (size_t)l * 128 * 128;
        size_t bOff = (size_t)l * 128;
        zero_accum_kernel<<<(N_NODES * 128 + 255) / 256, 256>>>();
        node_gemm_kernel<<<dim3((N_NODES + 127) / 128, 4), 256, 131072>>>(
            Wq + wOff, Wk + wOff, Wv + wOff, Ws + wOff,
            bq + bOff, bk + bOff, bv + bOff, bs + bOff);
        edge_kernel<<<N_EDGES / 128, 256, 132096>>>(We + wOff);
        update_h_kernel<<<(N_NODES * 128 + 255) / 256, 256>>>();
    }
    out_gemm_kernel<<<N_NODES / 16, 256>>>(Wout, bout, out);
}

// round 7
// speedup vs baseline: 1.4356x; 1.2626x over previous
#include <cuda_runtime.h>
#include <cuda_bf16.h>
#include <math.h>
#include <stdint.h>

#define N_NODES 100000
#define N_EDGES 800000
#define N_NTILE 782
#define N_ETILE 6250

// ---------------- device scratch ----------------
__device__ float g_h[(size_t)N_NODES * 128];
__device__ float g_ea[(size_t)N_EDGES * 128];    // edge features, dst-sorted order
__device__ float g_q[(size_t)N_NODES * 128];
__device__ float g_k[(size_t)N_NODES * 128];
__device__ float g_v[(size_t)N_NODES * 128];
__device__ float g_skip[(size_t)N_NODES * 128];
__device__ float g_numer[(size_t)N_NODES * 128];
__device__ float g_denom[(size_t)N_NODES * 8];
__device__ float g_wT[(size_t)15 * 16384];       // n-major transposed weights (3 layers x {q,k,v,s,e})
// sort scratch
__device__ int g_count[N_NODES];
__device__ int g_off2[N_NODES];
__device__ int g_src_s[N_EDGES];
__device__ int g_dst_s[N_EDGES];
__device__ int g_perm[N_EDGES];

// ---------------- smem layout constants ----------------
// bf16 tiles: 128 rows x 136 bf16 (272B row stride, conflict-free ldmatrix)
#define TROW 272
#define TBYTES 34816            // 128*272
#define OFF_AHI 0
#define OFF_ALO 34816
#define OFF_BHI 69632
#define OFF_BLO 104448
#define OFF_X   139264          // bias (node) / estage overlays B (edge) / src-dst (edge)

// ---------------- PTX helpers ----------------
__device__ __forceinline__ uint32_t smem_u32(const void* p) {
    uint32_t a;
    asm("{ .reg .u64 t; cvta.to.shared.u64 t, %1; cvt.u32.u64 %0, t; }" : "=r"(a) : "l"(p));
    return a;
}
__device__ __forceinline__ void ldsm4(uint32_t* r, uint32_t addr) {
    asm volatile("ldmatrix.sync.aligned.m8n8.x4.shared.b16 {%0,%1,%2,%3}, [%4];"
                 : "=r"(r[0]), "=r"(r[1]), "=r"(r[2]), "=r"(r[3]) : "r"(addr));
}
__device__ __forceinline__ void mma16816(float* c, const uint32_t* a, uint32_t b0, uint32_t b1) {
    asm volatile("mma.sync.aligned.m16n8k16.row.col.f32.bf16.bf16.f32 "
                 "{%0,%1,%2,%3}, {%4,%5,%6,%7}, {%8,%9}, {%0,%1,%2,%3};"
                 : "+f"(c[0]), "+f"(c[1]), "+f"(c[2]), "+f"(c[3])
                 : "r"(a[0]), "r"(a[1]), "r"(a[2]), "r"(a[3]), "r"(b0), "r"(b1));
}
__device__ __forceinline__ void red_add4(float* addr, float a, float b, float c, float d) {
    asm volatile("red.global.add.v4.f32 [%0], {%1, %2, %3, %4};"
                 :: "l"(addr), "f"(a), "f"(b), "f"(c), "f"(d) : "memory");
}
__device__ __forceinline__ float pe_val(int t, int c) {
    int j = c >> 1;
    float freq = expf(-logf(10000.0f) * (float)(2 * j) * (1.0f / 16.0f));
    float ang = (float)t * freq;
    return (c & 1) ? cosf(ang) : sinf(ang);
}
// split 8 floats -> bf16 hi/lo, store 16B each
__device__ __forceinline__ void split_store8(unsigned char* hi, unsigned char* lo, int off, const float* v) {
    unsigned int h[4], l[4];
#pragma unroll
    for (int i = 0; i < 4; ++i) {
        __nv_bfloat16 h0 = __float2bfloat16(v[2 * i]);
        __nv_bfloat16 h1 = __float2bfloat16(v[2 * i + 1]);
        __nv_bfloat16 l0 = __float2bfloat16(v[2 * i] - __bfloat162float(h0));
        __nv_bfloat16 l1 = __float2bfloat16(v[2 * i + 1] - __bfloat162float(h1));
        h[i] = (unsigned int)__bfloat16_as_ushort(h0) | ((unsigned int)__bfloat16_as_ushort(h1) << 16);
        l[i] = (unsigned int)__bfloat16_as_ushort(l0) | ((unsigned int)__bfloat16_as_ushort(l1) << 16);
    }
    *(uint4*)(hi + off) = make_uint4(h[0], h[1], h[2], h[3]);
    *(uint4*)(lo + off) = make_uint4(l[0], l[1], l[2], l[3]);
}
// convert a 128x128 f32 gmem tile (row-major, stride 128) into hi/lo bf16 smem tiles
__device__ __forceinline__ void cvt_tile(const float* __restrict__ g, int validRows,
                                         unsigned char* hi, unsigned char* lo, int tid) {
#pragma unroll
    for (int it = 0; it < 8; ++it) {
        int c = it * 256 + tid;
        int row = c >> 4, seg = (c & 15) << 3;
        float v[8];
        if (row < validRows) {
            float4 a = *(const float4*)(g + (size_t)row * 128 + seg);
            float4 b = *(const float4*)(g + (size_t)row * 128 + seg + 4);
            v[0] = a.x; v[1] = a.y; v[2] = a.z; v[3] = a.w;
            v[4] = b.x; v[5] = b.y; v[6] = b.z; v[7] = b.w;
        } else {
#pragma unroll
            for (int i = 0; i < 8; ++i) v[i] = 0.0f;
        }
        split_store8(hi, lo, row * TROW + seg * 2, v);
    }
}

// 3-pass split-bf16 GEMM: warp (wr, wc) accumulates C[wr*32..+32][wc*64..+64] into c[2][8][4]
__device__ __forceinline__ void gemm3(uint32_t aHi, uint32_t aLo, uint32_t bHi, uint32_t bLo,
                                      int lane, int wr, int wc, float c[2][8][4]) {
    int rA = lane & 15;
    int kA = (lane >> 4) << 3;
    int rB = ((lane >> 4) << 3) + (lane & 7);
    int kB = ((lane >> 3) & 1) << 3;
    uint32_t aRow = (uint32_t)(wr * 32 + rA) * TROW;
    uint32_t bRow = (uint32_t)(wc * 64 + rB) * TROW;
    for (int pass = 0; pass < 3; ++pass) {
        uint32_t aB = (pass < 2) ? aHi : aLo;
        uint32_t bB = (pass == 1) ? bLo : bHi;
#pragma unroll
        for (int k16 = 0; k16 < 8; ++k16) {
            uint32_t ka = (uint32_t)(k16 * 16 + kA) * 2;
            uint32_t kb = (uint32_t)(k16 * 16 + kB) * 2;
            uint32_t a[2][4];
            ldsm4(a[0], aB + aRow + ka);
            ldsm4(a[1], aB + aRow + 16 * TROW + ka);
            uint32_t b[4][4];
#pragma unroll
            for (int p = 0; p < 4; ++p) ldsm4(b[p], bB + bRow + p * 16 * TROW + kb);
#pragma unroll
            for (int t = 0; t < 2; ++t)
#pragma unroll
                for (int nt = 0; nt < 8; ++nt)
                    mma16816(c[t][nt], a[t], b[nt >> 1][(nt & 1) * 2], b[nt >> 1][(nt & 1) * 2 + 1]);
        }
    }
}

// ---------------- sort-by-dst ----------------
__global__ void zero_count_kernel() {
    int i = blockIdx.x * blockDim.x + threadIdx.x;
    if (i < N_NODES) g_count[i] = 0;
}
__global__ void hist_kernel(const int* __restrict__ ei) {
    int e = blockIdx.x * blockDim.x + threadIdx.x;
    if (e < N_EDGES) atomicAdd(&g_count[ei[N_EDGES + e]], 1);
}
__global__ void scan_kernel() {
    __shared__ int warp_sums[32];
    __shared__ int s_carry;
    int tid = threadIdx.x;
    int lane = tid & 31, wid = tid >> 5;
    if (tid == 0) s_carry = 0;
    __syncthreads();
    for (int base = 0; base < N_NODES; base += 1024) {
        int idx = base + tid;
        int v = (idx < N_NODES) ? g_count[idx] : 0;
        int inc = v;
#pragma unroll
        for (int o = 1; o < 32; o <<= 1) {
            int t = __shfl_up_sync(0xffffffffu, inc, o);
            if (lane >= o) inc += t;
        }
        if (lane == 31) warp_sums[wid] = inc;
        __syncthreads();
        if (wid == 0) {
            int w = warp_sums[lane];
            int wi = w;
#pragma unroll
            for (int o = 1; o < 32; o <<= 1) {
                int t = __shfl_up_sync(0xffffffffu, wi, o);
                if (lane >= o) wi += t;
            }
            warp_sums[lane] = wi - w;
        }
        __syncthreads();
        int ex = inc - v + warp_sums[wid] + s_carry;
        if (idx < N_NODES) g_off2[idx] = ex;
        __syncthreads();
        if (tid == 1023) s_carry = ex + v;
        __syncthreads();
    }
}
__global__ void scatter_kernel(const int* __restrict__ ei) {
    int e = blockIdx.x * blockDim.x + threadIdx.x;
    if (e >= N_EDGES) return;
    int d = ei[N_EDGES + e];
    int pos = atomicAdd(&g_off2[d], 1);
    g_src_s[pos] = ei[e];
    g_dst_s[pos] = d;
    g_perm[pos] = e;
}

// ---------------- builders ----------------
__global__ void build_h_kernel(const float* __restrict__ x, const int* __restrict__ nlu) {
    int idx = blockIdx.x * blockDim.x + threadIdx.x;
    if (idx >= N_NODES * 128) return;
    int d = idx & 127;
    int n = idx >> 7;
    float v;
    if (d < 96) v = x[n * 96 + d];
    else {
        int dd = d - 96;
        v = pe_val(nlu[n * 2 + (dd >> 4)], dd & 15);
    }
    g_h[idx] = v;
}
__global__ void build_ea_kernel(const float* __restrict__ eattr, const int* __restrict__ elu) {
    long long idx = (long long)blockIdx.x * blockDim.x + threadIdx.x;
    if (idx >= (long long)N_EDGES * 128) return;
    int d = (int)(idx & 127);
    int p = (int)(idx >> 7);
    int e = g_perm[p];
    float v;
    if (d < 96) v = eattr[(size_t)e * 96 + d];
    else {
        int dd = d - 96;
        v = pe_val(elu[(size_t)e * 2 + (dd >> 4)], dd & 15);
    }
    g_ea[idx] = v;
}
// transpose weights to n-major: g_wT[t][n][k] = W_l[k][n], t = layer*5 + {q,k,v,s,e}
__global__ void prep_wT_kernel(const float* __restrict__ Wq, const float* __restrict__ Wk,
                               const float* __restrict__ Wv, const float* __restrict__ Ws,
                               const float* __restrict__ We) {
    int gid = blockIdx.x * blockDim.x + threadIdx.x;
    if (gid >= 15 * 16384) return;
    int t = gid >> 14, rem = gid & 16383;
    int n = rem >> 7, k = rem & 127;
    int l = t / 5, m = t % 5;
    const float* W = (m == 0) ? Wq : (m == 1) ? Wk : (m == 2) ? Wv : (m == 3) ? Ws : We;
    g_wT[(size_t)t * 16384 + n * 128 + k] = W[(size_t)l * 16384 + k * 128 + n];
}
__global__ void zero_accum_kernel() {
    int idx = blockIdx.x * blockDim.x + threadIdx.x;
    if (idx < N_NODES * 128) g_numer[idx] = 0.0f;
    if (idx < N_NODES * 8)  g_denom[idx] = 0.0f;
}

// ---------------- node GEMM via mma.sync (4 outputs per block, serial) ----------------
__global__ __launch_bounds__(256, 1)
void node_mma_kernel(const float* __restrict__ bq, const float* __restrict__ bk,
                     const float* __restrict__ bv, const float* __restrict__ bsk, int layer) {
    extern __shared__ __align__(16) unsigned char smem[];
    uint32_t sb = smem_u32(smem);
    int tid = threadIdx.x, wid = tid >> 5, lane = tid & 31;
    int wr = wid & 3, wc = wid >> 2;
    int tile = blockIdx.x;
    int validRows = N_NODES - tile * 128;
    if (validRows > 128) validRows = 128;

    cvt_tile(g_h + (size_t)tile * 128 * 128, validRows, smem + OFF_AHI, smem + OFF_ALO, tid);

    float* biasBuf = (float*)(smem + OFF_X);
    int gi = lane >> 2, tig = lane & 3;

    for (int w = 0; w < 4; ++w) {
        __syncthreads();   // previous epilogue done before overwriting B / bias
        const float* wT = g_wT + (size_t)(layer * 5 + w) * 16384;
        cvt_tile(wT, 128, smem + OFF_BHI, smem + OFF_BLO, tid);
        if (tid < 128) {
            const float* bias = (w == 0) ? bq : (w == 1) ? bk : (w == 2) ? bv : bsk;
            biasBuf[tid] = bias[layer * 128 + tid];
        }
        __syncthreads();

        float c[2][8][4];
#pragma unroll
        for (int t = 0; t < 2; ++t)
#pragma unroll
            for (int nt = 0; nt < 8; ++nt)
#pragma unroll
                for (int j = 0; j < 4; ++j) c[t][nt][j] = 0.0f;

        gemm3(sb + OFF_AHI, sb + OFF_ALO, sb + OFF_BHI, sb + OFF_BLO, lane, wr, wc, c);

        float* out = (w == 0) ? g_q : (w == 1) ? g_k : (w == 2) ? g_v : g_skip;
#pragma unroll
        for (int t = 0; t < 2; ++t) {
#pragma unroll
            for (int half = 0; half < 2; ++half) {
                int node = tile * 128 + wr * 32 + t * 16 + gi + half * 8;
                if (node < N_NODES) {
                    float* op = out + (size_t)node * 128;
#pragma unroll
                    for (int nt = 0; nt < 8; ++nt) {
                        int col = wc * 64 + nt * 8 + tig * 2;
                        float2 val = make_float2(c[t][nt][half * 2 + 0] + biasBuf[col],
                                                 c[t][nt][half * 2 + 1] + biasBuf[col + 1]);
                        *(float2*)(op + col) = val;
                    }
                }
            }
        }
    }
}

// ---------------- fused edge kernel: mma GEMM + gather/softmax/atomic epilogue ----------------
__global__ __launch_bounds__(256, 1)
void edge_mma_kernel(int layer) {
    extern __shared__ __align__(16) unsigned char smem[];
    uint32_t sb = smem_u32(smem);
    int tid = threadIdx.x, wid = tid >> 5, lane = tid & 31;
    int wr = wid & 3, wc = wid >> 2;
    int tile = blockIdx.x;
    int e0 = tile << 7;

    cvt_tile(g_ea + (size_t)e0 * 128, 128, smem + OFF_AHI, smem + OFF_ALO, tid);
    cvt_tile(g_wT + (size_t)(layer * 5 + 4) * 16384, 128, smem + OFF_BHI, smem + OFF_BLO, tid);
    int* s_src = (int*)(smem + OFF_X);
    int* s_dst = (int*)(smem + OFF_X + 512);
    if (tid < 128) {
        s_src[tid] = g_src_s[e0 + tid];
        s_dst[tid] = g_dst_s[e0 + tid];
    }
    __syncthreads();

    float c[2][8][4];
#pragma unroll
    for (int t = 0; t < 2; ++t)
#pragma unroll
        for (int nt = 0; nt < 8; ++nt)
#pragma unroll
            for (int j = 0; j < 4; ++j) c[t][nt][j] = 0.0f;

    gemm3(sb + OFF_AHI, sb + OFF_ALO, sb + OFF_BHI, sb + OFF_BLO, lane, wr, wc, c);

    __syncthreads();   // all warps done reading B before estage overwrites it
    float* est = (float*)(smem + OFF_BHI);  // 128 x 132 floats (67584B <= 69632B of B region)
    int gi = lane >> 2, tig = lane & 3;
#pragma unroll
    for (int t = 0; t < 2; ++t)
#pragma unroll
        for (int half = 0; half < 2; ++half) {
            int r = wr * 32 + t * 16 + gi + half * 8;
#pragma unroll
            for (int nt = 0; nt < 8; ++nt) {
                int col = wc * 64 + nt * 8 + tig * 2;
                *(float2*)(est + r * 132 + col) = make_float2(c[t][nt][half * 2], c[t][nt][half * 2 + 1]);
            }
        }
    __syncthreads();

    // proven epilogue: thread (tx,ty) -> edges ty*8+i, cols tx*8..+7
    int tx = tid & 15, ty = tid >> 4;
    int hd = tx >> 1;
    int cb = tx << 3;
    int cur_d = -1;
    float aN0 = 0.f, aN1 = 0.f, aN2 = 0.f, aN3 = 0.f;
    float aN4 = 0.f, aN5 = 0.f, aN6 = 0.f, aN7 = 0.f;
    float aD = 0.f;
#pragma unroll
    for (int i = 0; i < 8; ++i) {
        int er = ty * 8 + i;
        float4 e0v = *(const float4*)(est + er * 132 + cb);
        float4 e1v = *(const float4*)(est + er * 132 + cb + 4);
        float e8[8] = {e0v.x, e0v.y, e0v.z, e0v.w, e1v.x, e1v.y, e1v.z, e1v.w};
        int s = s_src[er], d = s_dst[er];
        const float* qp = g_q + (size_t)d * 128 + cb;
        const float* kp = g_k + (size_t)s * 128 + cb;
        float4 q0 = *(const float4*)qp, q1 = *(const float4*)(qp + 4);
        float4 k0 = *(const float4*)kp, k1 = *(const float4*)(kp + 4);
        float part = q0.x * (k0.x + e8[0]) + q0.y * (k0.y + e8[1])
                   + q0.z * (k0.z + e8[2]) + q0.w * (k0.w + e8[3])
                   + q1.x * (k1.x + e8[4]) + q1.y * (k1.y + e8[5])
                   + q1.z * (k1.z + e8[6]) + q1.w * (k1.w + e8[7]);
        float full = part + __shfl_xor_sync(0xffffffffu, part, 1);
        float p = expf(full * 0.25f);  // shift-free softmax (alpha is O(1))
        if (d != cur_d) {
            if (cur_d >= 0) {
                float* np = g_numer + (size_t)cur_d * 128 + cb;
                red_add4(np,     aN0, aN1, aN2, aN3);
                red_add4(np + 4, aN4, aN5, aN6, aN7);
                if (!(tx & 1)) atomicAdd(g_denom + (size_t)cur_d * 8 + hd, aD);
            }
            cur_d = d;
            aN0 = aN1 = aN2 = aN3 = aN4 = aN5 = aN6 = aN7 = 0.f;
            aD = 0.f;
        }
        const float* vp = g_v + (size_t)s * 128 + cb;
        float4 v0 = *(const float4*)vp, v1 = *(const float4*)(vp + 4);
        aN0 += p * (v0.x + e8[0]); aN1 += p * (v0.y + e8[1]);
        aN2 += p * (v0.z + e8[2]); aN3 += p * (v0.w + e8[3]);
        aN4 += p * (v1.x + e8[4]); aN5 += p * (v1.y + e8[5]);
        aN6 += p * (v1.z + e8[6]); aN7 += p * (v1.w + e8[7]);
        aD += p;
    }
    {
        float* np = g_numer + (size_t)cur_d * 128 + cb;
        red_add4(np,     aN0, aN1, aN2, aN3);
        red_add4(np + 4, aN4, aN5, aN6, aN7);
        if (!(tx & 1)) atomicAdd(g_denom + (size_t)cur_d * 8 + hd, aD);
    }
}

// ---------------- node update ----------------
__global__ void update_h_kernel() {
    int idx = blockIdx.x * blockDim.x + threadIdx.x;
    if (idx >= N_NODES * 128) return;
    int n = idx >> 7;
    int c = idx & 127;
    float den = g_denom[n * 8 + (c >> 4)];
    float v = g_numer[idx] / (den + 1e-16f) + g_skip[idx];
    g_h[idx] = fmaxf(v, 0.0f);
}

// ---------------- output GEMM ----------------
__global__ void out_gemm_kernel(const float* __restrict__ Wout, const float* __restrict__ bout,
                                float* __restrict__ out) {
    __shared__ float ws[128 * 16];
    __shared__ float hs[16 * 128];
    int tid = threadIdx.x;
    int row0 = blockIdx.x * 16;
#pragma unroll
    for (int it = 0; it < 8; ++it) {
        int idx = it * 256 + tid;
        ws[idx] = Wout[idx];
        int r = row0 + (idx >> 7);
        hs[idx] = (r < N_NODES) ? g_h[(size_t)row0 * 128 + idx] : 0.0f;
    }
    __syncthreads();
    int r = tid >> 4, c = tid & 15;
    float s = bout[c];
#pragma unroll 8
    for (int k = 0; k < 128; ++k) s += hs[r * 128 + k] * ws[k * 16 + c];
    int gr = row0 + r;
    if (gr < N_NODES) out[(size_t)gr * 16 + c] = s;
}

// ---------------- host ----------------
extern "C" void kernel_launch(void* const* d_in, const int* in_sizes, int n_in,
                              void* d_out, int out_size) {
    const float* x     = (const float*)d_in[0];
    const int*   nlu   = (const int*)  d_in[1];
    const int*   ei    = (const int*)  d_in[2];
    const float* eattr = (const float*)d_in[3];
    const int*   elu   = (const int*)  d_in[4];
    const float* Wq    = (const float*)d_in[5];
    const float* bq    = (const float*)d_in[6];
    const float* Wk    = (const float*)d_in[7];
    const float* bk    = (const float*)d_in[8];
    const float* Wv    = (const float*)d_in[9];
    const float* bv    = (const float*)d_in[10];
    const float* We    = (const float*)d_in[11];
    const float* Ws    = (const float*)d_in[12];
    const float* bs    = (const float*)d_in[13];
    const float* Wout  = (const float*)d_in[14];
    const float* bout  = (const float*)d_in[15];
    float* out = (float*)d_out;
    (void)in_sizes; (void)n_in; (void)out_size;

    const int SMEM_NODE = OFF_X + 1024;   // 140288
    const int SMEM_EDGE = OFF_X + 1024;   // 140288
    cudaFuncSetAttribute(node_mma_kernel, cudaFuncAttributeMaxDynamicSharedMemorySize, SMEM_NODE);
    cudaFuncSetAttribute(edge_mma_kernel, cudaFuncAttributeMaxDynamicSharedMemorySize, SMEM_EDGE);

    // sort edges by dst
    zero_count_kernel<<<(N_NODES + 255) / 256, 256>>>();
    hist_kernel<<<(N_EDGES + 255) / 256, 256>>>(ei);
    scan_kernel<<<1, 1024>>>();
    scatter_kernel<<<(N_EDGES + 255) / 256, 256>>>(ei);

    build_h_kernel <<<(N_NODES * 128 + 255) / 256, 256>>>(x, nlu);
    build_ea_kernel<<<(int)(((long long)N_EDGES * 128 + 255) / 256), 256>>>(eattr, elu);
    prep_wT_kernel <<<(15 * 16384 + 255) / 256, 256>>>(Wq, Wk, Wv, Ws, We);

    for (int l = 0; l < 3; ++l) {
        zero_accum_kernel<<<(N_NODES * 128 + 255) / 256, 256>>>();
        node_mma_kernel<<<N_NTILE, 256, SMEM_NODE>>>(bq, bk, bv, bs, l);
        edge_mma_kernel<<<N_ETILE, 256, SMEM_EDGE>>>(l);
        update_h_kernel<<<(N_NODES * 128 + 255) / 256, 256>>>();
    }
    out_gemm_kernel<<<N_NODES / 16, 256>>>(Wout, bout, out);
}

// round 8
// speedup vs baseline: 1.8026x; 1.2557x over previous
#include <cuda_runtime.h>
#include <cuda_bf16.h>
#include <math.h>
#include <stdint.h>

#define N_NODES 100000
#define N_EDGES 800000
#define N_NTILE 782
#define N_ETILE 6250

// bf16 tile image: 128 rows x 136 bf16 (272B stride); hi tile then lo tile
#define TROW 272
#define TBYTES 34816
#define IMGB 69632

// ---------------- device scratch ----------------
__device__ float g_h[(size_t)N_NODES * 128];
__device__ float g_q[(size_t)N_NODES * 128];
__device__ float g_k[(size_t)N_NODES * 128];
__device__ float g_v[(size_t)N_NODES * 128];
__device__ float g_skip[(size_t)N_NODES * 128];
__device__ float g_numer[(size_t)N_NODES * 128];
__device__ float g_denom[(size_t)N_NODES * 8];
// pre-built bf16 hi/lo operand images (exact smem tile layout)
__device__ unsigned char g_himg[(size_t)N_NTILE * IMGB];
__device__ unsigned char g_eaimg[(size_t)N_ETILE * IMGB];
__device__ unsigned char g_wimg[(size_t)15 * IMGB];
// sort scratch
__device__ int g_count[N_NODES];
__device__ int g_off2[N_NODES];
__device__ int g_src_s[N_EDGES];
__device__ int g_dst_s[N_EDGES];
__device__ int g_perm[N_EDGES];

// ---------------- PTX helpers ----------------
__device__ __forceinline__ uint32_t smem_u32(const void* p) {
    uint32_t a;
    asm("{ .reg .u64 t; cvta.to.shared.u64 t, %1; cvt.u32.u64 %0, t; }" : "=r"(a) : "l"(p));
    return a;
}
__device__ __forceinline__ void ldsm4(uint32_t* r, uint32_t addr) {
    asm volatile("ldmatrix.sync.aligned.m8n8.x4.shared.b16 {%0,%1,%2,%3}, [%4];"
                 : "=r"(r[0]), "=r"(r[1]), "=r"(r[2]), "=r"(r[3]) : "r"(addr));
}
__device__ __forceinline__ void mma16816(float* c, const uint32_t* a, uint32_t b0, uint32_t b1) {
    asm volatile("mma.sync.aligned.m16n8k16.row.col.f32.bf16.bf16.f32 "
                 "{%0,%1,%2,%3}, {%4,%5,%6,%7}, {%8,%9}, {%0,%1,%2,%3};"
                 : "+f"(c[0]), "+f"(c[1]), "+f"(c[2]), "+f"(c[3])
                 : "r"(a[0]), "r"(a[1]), "r"(a[2]), "r"(a[3]), "r"(b0), "r"(b1));
}
__device__ __forceinline__ void red_add4(float* addr, float a, float b, float c, float d) {
    asm volatile("red.global.add.v4.f32 [%0], {%1, %2, %3, %4};"
                 :: "l"(addr), "f"(a), "f"(b), "f"(c), "f"(d) : "memory");
}
__device__ __forceinline__ float pe_val(int t, int c) {
    int j = c >> 1;
    float freq = expf(-logf(10000.0f) * (float)(2 * j) * (1.0f / 16.0f));
    float ang = (float)t * freq;
    return (c & 1) ? cosf(ang) : sinf(ang);
}
// split 8 floats -> hi at off, lo at off+TBYTES within an image
__device__ __forceinline__ void split_store8(unsigned char* img, int off, const float* v) {
    unsigned int h[4], l[4];
#pragma unroll
    for (int i = 0; i < 4; ++i) {
        __nv_bfloat16 h0 = __float2bfloat16(v[2 * i]);
        __nv_bfloat16 h1 = __float2bfloat16(v[2 * i + 1]);
        __nv_bfloat16 l0 = __float2bfloat16(v[2 * i] - __bfloat162float(h0));
        __nv_bfloat16 l1 = __float2bfloat16(v[2 * i + 1] - __bfloat162float(h1));
        h[i] = (unsigned int)__bfloat16_as_ushort(h0) | ((unsigned int)__bfloat16_as_ushort(h1) << 16);
        l[i] = (unsigned int)__bfloat16_as_ushort(l0) | ((unsigned int)__bfloat16_as_ushort(l1) << 16);
    }
    *(uint4*)(img + off) = make_uint4(h[0], h[1], h[2], h[3]);
    *(uint4*)(img + TBYTES + off) = make_uint4(l[0], l[1], l[2], l[3]);
}

// 3-pass split-bf16 GEMM: warp (wr, wc) -> C[wr*32..+32][wc*64..+64] in c[2][8][4]
__device__ __forceinline__ void gemm3(uint32_t aHi, uint32_t aLo, uint32_t bHi, uint32_t bLo,
                                      int lane, int wr, int wc, float c[2][8][4]) {
    int rA = lane & 15;
    int kA = (lane >> 4) << 3;
    int rB = ((lane >> 4) << 3) + (lane & 7);
    int kB = ((lane >> 3) & 1) << 3;
    uint32_t aRow = (uint32_t)(wr * 32 + rA) * TROW;
    uint32_t bRow = (uint32_t)(wc * 64 + rB) * TROW;
    for (int pass = 0; pass < 3; ++pass) {
        uint32_t aB = (pass < 2) ? aHi : aLo;
        uint32_t bB = (pass == 1) ? bLo : bHi;
#pragma unroll
        for (int k16 = 0; k16 < 8; ++k16) {
            uint32_t ka = (uint32_t)(k16 * 16 + kA) * 2;
            uint32_t kb = (uint32_t)(k16 * 16 + kB) * 2;
            uint32_t a[2][4];
            ldsm4(a[0], aB + aRow + ka);
            ldsm4(a[1], aB + aRow + 16 * TROW + ka);
            uint32_t b[4][4];
#pragma unroll
            for (int p = 0; p < 4; ++p) ldsm4(b[p], bB + bRow + p * 16 * TROW + kb);
#pragma unroll
            for (int t = 0; t < 2; ++t)
#pragma unroll
                for (int nt = 0; nt < 8; ++nt)
                    mma16816(c[t][nt], a[t], b[nt >> 1][(nt & 1) * 2], b[nt >> 1][(nt & 1) * 2 + 1]);
        }
    }
}

// ---------------- sort-by-dst ----------------
__global__ void zero_count_kernel() {
    int i = blockIdx.x * blockDim.x + threadIdx.x;
    if (i < N_NODES) g_count[i] = 0;
}
__global__ void hist_kernel(const int* __restrict__ ei) {
    int e = blockIdx.x * blockDim.x + threadIdx.x;
    if (e < N_EDGES) atomicAdd(&g_count[ei[N_EDGES + e]], 1);
}
__global__ void scan_kernel() {
    __shared__ int warp_sums[32];
    __shared__ int s_carry;
    int tid = threadIdx.x;
    int lane = tid & 31, wid = tid >> 5;
    if (tid == 0) s_carry = 0;
    __syncthreads();
    for (int base = 0; base < N_NODES; base += 1024) {
        int idx = base + tid;
        int v = (idx < N_NODES) ? g_count[idx] : 0;
        int inc = v;
#pragma unroll
        for (int o = 1; o < 32; o <<= 1) {
            int t = __shfl_up_sync(0xffffffffu, inc, o);
            if (lane >= o) inc += t;
        }
        if (lane == 31) warp_sums[wid] = inc;
        __syncthreads();
        if (wid == 0) {
            int w = warp_sums[lane];
            int wi = w;
#pragma unroll
            for (int o = 1; o < 32; o <<= 1) {
                int t = __shfl_up_sync(0xffffffffu, wi, o);
                if (lane >= o) wi += t;
            }
            warp_sums[lane] = wi - w;
        }
        __syncthreads();
        int ex = inc - v + warp_sums[wid] + s_carry;
        if (idx < N_NODES) g_off2[idx] = ex;
        __syncthreads();
        if (tid == 1023) s_carry = ex + v;
        __syncthreads();
    }
}
__global__ void scatter_kernel(const int* __restrict__ ei) {
    int e = blockIdx.x * blockDim.x + threadIdx.x;
    if (e >= N_EDGES) return;
    int d = ei[N_EDGES + e];
    int pos = atomicAdd(&g_off2[d], 1);
    g_src_s[pos] = ei[e];
    g_dst_s[pos] = d;
    g_perm[pos] = e;
}

// ---------------- builders (write bf16 hi/lo images) ----------------
__global__ void build_h_kernel(const float* __restrict__ x, const int* __restrict__ nlu) {
    int gid = blockIdx.x * blockDim.x + threadIdx.x;
    if (gid >= N_NODES * 16) return;
    int n = gid >> 4, j = gid & 15, c0 = j * 8;
    float v[8];
    if (c0 < 96) {
        float4 a = *(const float4*)(x + (size_t)n * 96 + c0);
        float4 b = *(const float4*)(x + (size_t)n * 96 + c0 + 4);
        v[0] = a.x; v[1] = a.y; v[2] = a.z; v[3] = a.w; v[4] = b.x; v[5] = b.y; v[6] = b.z; v[7] = b.w;
    } else {
        int t = nlu[n * 2 + ((c0 - 96) >> 4)];
        int cl = (c0 - 96) & 15;
#pragma unroll
        for (int i = 0; i < 8; ++i) v[i] = pe_val(t, cl + i);
    }
    split_store8(g_himg + (size_t)(n >> 7) * IMGB, (n & 127) * TROW + c0 * 2, v);
}
__global__ void build_eaimg_kernel(const float* __restrict__ eattr, const int* __restrict__ elu) {
    int gid = blockIdx.x * blockDim.x + threadIdx.x;
    if (gid >= N_EDGES * 16) return;
    int p = gid >> 4, j = gid & 15, c0 = j * 8;
    int e = g_perm[p];
    float v[8];
    if (c0 < 96) {
        float4 a = *(const float4*)(eattr + (size_t)e * 96 + c0);
        float4 b = *(const float4*)(eattr + (size_t)e * 96 + c0 + 4);
        v[0] = a.x; v[1] = a.y; v[2] = a.z; v[3] = a.w; v[4] = b.x; v[5] = b.y; v[6] = b.z; v[7] = b.w;
    } else {
        int t = elu[(size_t)e * 2 + ((c0 - 96) >> 4)];
        int cl = (c0 - 96) & 15;
#pragma unroll
        for (int i = 0; i < 8; ++i) v[i] = pe_val(t, cl + i);
    }
    split_store8(g_eaimg + (size_t)(p >> 7) * IMGB, (p & 127) * TROW + c0 * 2, v);
}
// weight images (n-major rows): image row n, cols k; t = layer*5 + {q,k,v,s,e}
__global__ void prep_w_kernel(const float* __restrict__ Wq, const float* __restrict__ Wk,
                              const float* __restrict__ Wv, const float* __restrict__ Ws,
                              const float* __restrict__ We) {
    int gid = blockIdx.x * blockDim.x + threadIdx.x;
    if (gid >= 15 * 2048) return;
    int t = gid >> 11, rem = gid & 2047;
    int n = rem >> 4, j = rem & 15, k0 = j * 8;
    int l = t / 5, m = t % 5;
    const float* W = (m == 0) ? Wq : (m == 1) ? Wk : (m == 2) ? Wv : (m == 3) ? Ws : We;
    const float* base = W + (size_t)l * 16384;
    float v[8];
#pragma unroll
    for (int i = 0; i < 8; ++i) v[i] = base[(size_t)(k0 + i) * 128 + n];
    split_store8(g_wimg + (size_t)t * IMGB, n * TROW + k0 * 2, v);
}

// ---------------- node GEMM (2 GEMMs per block; operands are image memcpys) ----------------
#define OFF_NB 69632
#define OFF_NBIAS 139264
#define SMEM_NODE 139776
__global__ __launch_bounds__(256, 1)
void node_mma_kernel(const float* __restrict__ bq, const float* __restrict__ bk,
                     const float* __restrict__ bv, const float* __restrict__ bsk, int layer) {
    extern __shared__ __align__(16) unsigned char smem[];
    uint32_t sb = smem_u32(smem);
    int tid = threadIdx.x, wid = tid >> 5, lane = tid & 31;
    int wr = wid & 3, wc = wid >> 2;
    int tile = blockIdx.x, ysel = blockIdx.y;
    int gi = lane >> 2, tig = lane & 3;

    const uint4* aimg = (const uint4*)(g_himg + (size_t)tile * IMGB);
    uint4* sA = (uint4*)smem;
#pragma unroll
    for (int it = 0; it < 17; ++it) sA[it * 256 + tid] = aimg[it * 256 + tid];

    float* biasBuf = (float*)(smem + OFF_NBIAS);
    uint4* sB = (uint4*)(smem + OFF_NB);

    for (int w2 = 0; w2 < 2; ++w2) {
        int w = ysel * 2 + w2;
        __syncthreads();   // A ready / previous epilogue done
        const uint4* bimg = (const uint4*)(g_wimg + (size_t)(layer * 5 + w) * IMGB);
#pragma unroll
        for (int it = 0; it < 17; ++it) sB[it * 256 + tid] = bimg[it * 256 + tid];
        if (tid < 128) {
            const float* bias = (w == 0) ? bq : (w == 1) ? bk : (w == 2) ? bv : bsk;
            biasBuf[tid] = bias[layer * 128 + tid];
        }
        __syncthreads();

        float c[2][8][4];
#pragma unroll
        for (int t = 0; t < 2; ++t)
#pragma unroll
            for (int nt = 0; nt < 8; ++nt)
#pragma unroll
                for (int j = 0; j < 4; ++j) c[t][nt][j] = 0.0f;

        gemm3(sb, sb + TBYTES, sb + OFF_NB, sb + OFF_NB + TBYTES, lane, wr, wc, c);

        float* out = (w == 0) ? g_q : (w == 1) ? g_k : (w == 2) ? g_v : g_skip;
#pragma unroll
        for (int t = 0; t < 2; ++t) {
#pragma unroll
            for (int half = 0; half < 2; ++half) {
                int node = tile * 128 + wr * 32 + t * 16 + gi + half * 8;
                if (node < N_NODES) {
                    float* op = out + (size_t)node * 128;
#pragma unroll
                    for (int nt = 0; nt < 8; ++nt) {
                        int col = wc * 64 + nt * 8 + tig * 2;
                        *(float2*)(op + col) = make_float2(c[t][nt][half * 2 + 0] + biasBuf[col],
                                                           c[t][nt][half * 2 + 1] + biasBuf[col + 1]);
                    }
                }
            }
        }
    }
}

// ---------------- persistent fused edge kernel ----------------
#define OFF_EA 69632
#define OFF_EX 139264
#define SMEM_EDGE 140288
__global__ __launch_bounds__(256, 1)
void edge_mma_kernel(int layer) {
    extern __shared__ __align__(16) unsigned char smem[];
    uint32_t sb = smem_u32(smem);
    int tid = threadIdx.x, wid = tid >> 5, lane = tid & 31;
    int wr = wid & 3, wc = wid >> 2;
    int gi = lane >> 2, tig = lane & 3;
    int tx = tid & 15, ty = tid >> 4;
    int hd = tx >> 1, cb = tx << 3;

    // resident B (We image), loaded once
    const uint4* bimg = (const uint4*)(g_wimg + (size_t)(layer * 5 + 4) * IMGB);
    uint4* sB = (uint4*)smem;
#pragma unroll
    for (int it = 0; it < 17; ++it) sB[it * 256 + tid] = bimg[it * 256 + tid];

    uint4* sA = (uint4*)(smem + OFF_EA);
    float* est = (float*)(smem + OFF_EA);   // overlays A after GEMM
    int* s_src = (int*)(smem + OFF_EX);
    int* s_dst = (int*)(smem + OFF_EX + 512);

    for (int tile = blockIdx.x; tile < N_ETILE; tile += gridDim.x) {
        __syncthreads();   // prior epilogue done before overwriting A/estage/src
        const uint4* aimg = (const uint4*)(g_eaimg + (size_t)tile * IMGB);
#pragma unroll
        for (int it = 0; it < 17; ++it) sA[it * 256 + tid] = aimg[it * 256 + tid];
        int e0 = tile << 7;
        if (tid < 128) {
            s_src[tid] = g_src_s[e0 + tid];
            s_dst[tid] = g_dst_s[e0 + tid];
        }
        __syncthreads();

        float c[2][8][4];
#pragma unroll
        for (int t = 0; t < 2; ++t)
#pragma unroll
            for (int nt = 0; nt < 8; ++nt)
#pragma unroll
                for (int j = 0; j < 4; ++j) c[t][nt][j] = 0.0f;

        gemm3(sb + OFF_EA, sb + OFF_EA + TBYTES, sb, sb + TBYTES, lane, wr, wc, c);

        __syncthreads();   // all warps done reading A before estage overwrites it
#pragma unroll
        for (int t = 0; t < 2; ++t)
#pragma unroll
            for (int half = 0; half < 2; ++half) {
                int r = wr * 32 + t * 16 + gi + half * 8;
#pragma unroll
                for (int nt = 0; nt < 8; ++nt) {
                    int col = wc * 64 + nt * 8 + tig * 2;
                    *(float2*)(est + r * 132 + col) = make_float2(c[t][nt][half * 2], c[t][nt][half * 2 + 1]);
                }
            }
        __syncthreads();

        // run-coalesced softmax epilogue
        int cur_d = -1;
        float aN0 = 0.f, aN1 = 0.f, aN2 = 0.f, aN3 = 0.f;
        float aN4 = 0.f, aN5 = 0.f, aN6 = 0.f, aN7 = 0.f;
        float aD = 0.f;
#pragma unroll
        for (int i = 0; i < 8; ++i) {
            int er = ty * 8 + i;
            float4 e0v = *(const float4*)(est + er * 132 + cb);
            float4 e1v = *(const float4*)(est + er * 132 + cb + 4);
            float e8[8] = {e0v.x, e0v.y, e0v.z, e0v.w, e1v.x, e1v.y, e1v.z, e1v.w};
            int s = s_src[er], d = s_dst[er];
            const float* qp = g_q + (size_t)d * 128 + cb;
            const float* kp = g_k + (size_t)s * 128 + cb;
            float4 q0 = *(const float4*)qp, q1 = *(const float4*)(qp + 4);
            float4 k0 = *(const float4*)kp, k1 = *(const float4*)(kp + 4);
            float part = q0.x * (k0.x + e8[0]) + q0.y * (k0.y + e8[1])
                       + q0.z * (k0.z + e8[2]) + q0.w * (k0.w + e8[3])
                       + q1.x * (k1.x + e8[4]) + q1.y * (k1.y + e8[5])
                       + q1.z * (k1.z + e8[6]) + q1.w * (k1.w + e8[7]);
            float full = part + __shfl_xor_sync(0xffffffffu, part, 1);
            float p = expf(full * 0.25f);  // shift-free softmax (alpha is O(1))
            if (d != cur_d) {
                if (cur_d >= 0) {
                    float* np = g_numer + (size_t)cur_d * 128 + cb;
                    red_add4(np,     aN0, aN1, aN2, aN3);
                    red_add4(np + 4, aN4, aN5, aN6, aN7);
                    if (!(tx & 1)) atomicAdd(g_denom + (size_t)cur_d * 8 + hd, aD);
                }
                cur_d = d;
                aN0 = aN1 = aN2 = aN3 = aN4 = aN5 = aN6 = aN7 = 0.f;
                aD = 0.f;
            }
            const float* vp = g_v + (size_t)s * 128 + cb;
            float4 v0 = *(const float4*)vp, v1 = *(const float4*)(vp + 4);
            aN0 += p * (v0.x + e8[0]); aN1 += p * (v0.y + e8[1]);
            aN2 += p * (v0.z + e8[2]); aN3 += p * (v0.w + e8[3]);
            aN4 += p * (v1.x + e8[4]); aN5 += p * (v1.y + e8[5]);
            aN6 += p * (v1.z + e8[6]); aN7 += p * (v1.w + e8[7]);
            aD += p;
        }
        {
            float* np = g_numer + (size_t)cur_d * 128 + cb;
            red_add4(np,     aN0, aN1, aN2, aN3);
            red_add4(np + 4, aN4, aN5, aN6, aN7);
            if (!(tx & 1)) atomicAdd(g_denom + (size_t)cur_d * 8 + hd, aD);
        }
    }
}

// ---------------- node update: h = relu(numer/den + skip); rebuild images; re-zero accums ----------------
__global__ void update_h_kernel() {
    int gid = blockIdx.x * blockDim.x + threadIdx.x;
    if (gid >= N_NODES * 16) return;
    int n = gid >> 4, j = gid & 15, c0 = j * 8;
    float inv = 1.0f / (g_denom[n * 8 + (c0 >> 4)] + 1e-16f);
    float4 n0 = *(const float4*)(g_numer + (size_t)n * 128 + c0);
    float4 n1 = *(const float4*)(g_numer + (size_t)n * 128 + c0 + 4);
    float4 s0 = *(const float4*)(g_skip + (size_t)n * 128 + c0);
    float4 s1 = *(const float4*)(g_skip + (size_t)n * 128 + c0 + 4);
    float v[8];
    v[0] = fmaxf(n0.x * inv + s0.x, 0.f); v[1] = fmaxf(n0.y * inv + s0.y, 0.f);
    v[2] = fmaxf(n0.z * inv + s0.z, 0.f); v[3] = fmaxf(n0.w * inv + s0.w, 0.f);
    v[4] = fmaxf(n1.x * inv + s1.x, 0.f); v[5] = fmaxf(n1.y * inv + s1.y, 0.f);
    v[6] = fmaxf(n1.z * inv + s1.z, 0.f); v[7] = fmaxf(n1.w * inv + s1.w, 0.f);
    *(float4*)(g_h + (size_t)n * 128 + c0)     = make_float4(v[0], v[1], v[2], v[3]);
    *(float4*)(g_h + (size_t)n * 128 + c0 + 4) = make_float4(v[4], v[5], v[6], v[7]);
    split_store8(g_himg + (size_t)(n >> 7) * IMGB, (n & 127) * TROW + c0 * 2, v);
    // re-zero accumulators for next layer / next graph replay
    float4 z = make_float4(0.f, 0.f, 0.f, 0.f);
    *(float4*)(g_numer + (size_t)n * 128 + c0)     = z;
    *(float4*)(g_numer + (size_t)n * 128 + c0 + 4) = z;
    if (!(j & 1)) g_denom[n * 8 + (j >> 1)] = 0.0f;
}

// ---------------- output GEMM ----------------
__global__ void out_gemm_kernel(const float* __restrict__ Wout, const float* __restrict__ bout,
                                float* __restrict__ out) {
    __shared__ float ws[128 * 16];
    __shared__ float hs[16 * 128];
    int tid = threadIdx.x;
    int row0 = blockIdx.x * 16;
#pragma unroll
    for (int it = 0; it < 8; ++it) {
        int idx = it * 256 + tid;
        ws[idx] = Wout[idx];
        int r = row0 + (idx >> 7);
        hs[idx] = (r < N_NODES) ? g_h[(size_t)row0 * 128 + idx] : 0.0f;
    }
    __syncthreads();
    int r = tid >> 4, c = tid & 15;
    float s = bout[c];
#pragma unroll 8
    for (int k = 0; k < 128; ++k) s += hs[r * 128 + k] * ws[k * 16 + c];
    int gr = row0 + r;
    if (gr < N_NODES) out[(size_t)gr * 16 + c] = s;
}

// ---------------- host ----------------
extern "C" void kernel_launch(void* const* d_in, const int* in_sizes, int n_in,
                              void* d_out, int out_size) {
    const float* x     = (const float*)d_in[0];
    const int*   nlu   = (const int*)  d_in[1];
    const int*   ei    = (const int*)  d_in[2];
    const float* eattr = (const float*)d_in[3];
    const int*   elu   = (const int*)  d_in[4];
    const float* Wq    = (const float*)d_in[5];
    const float* bq    = (const float*)d_in[6];
    const float* Wk    = (const float*)d_in[7];
    const float* bk    = (const float*)d_in[8];
    const float* Wv    = (const float*)d_in[9];
    const float* bv    = (const float*)d_in[10];
    const float* We    = (const float*)d_in[11];
    const float* Ws    = (const float*)d_in[12];
    const float* bs    = (const float*)d_in[13];
    const float* Wout  = (const float*)d_in[14];
    const float* bout  = (const float*)d_in[15];
    float* out = (float*)d_out;
    (void)in_sizes; (void)n_in; (void)out_size;

    cudaFuncSetAttribute(node_mma_kernel, cudaFuncAttributeMaxDynamicSharedMemorySize, SMEM_NODE);
    cudaFuncSetAttribute(edge_mma_kernel, cudaFuncAttributeMaxDynamicSharedMemorySize, SMEM_EDGE);

    // sort edges by dst
    zero_count_kernel<<<(N_NODES + 255) / 256, 256>>>();
    hist_kernel<<<(N_EDGES + 255) / 256, 256>>>(ei);
    scan_kernel<<<1, 1024>>>();
    scatter_kernel<<<(N_EDGES + 255) / 256, 256>>>(ei);

    build_h_kernel   <<<(N_NODES * 16 + 255) / 256, 256>>>(x, nlu);
    build_eaimg_kernel<<<(N_EDGES * 16 + 255) / 256, 256>>>(eattr, elu);
    prep_w_kernel    <<<(15 * 2048 + 255) / 256, 256>>>(Wq, Wk, Wv, Ws, We);

    for (int l = 0; l < 3; ++l) {
        node_mma_kernel<<<dim3(N_NTILE, 2), 256, SMEM_NODE>>>(bq, bk, bv, bs, l);
        edge_mma_kernel<<<148, 256, SMEM_EDGE>>>(l);
        update_h_kernel<<<(N_NODES * 16 + 255) / 256, 256>>>();
    }
    out_gemm_kernel<<<N_NODES / 16, 256>>>(Wout, bout, out);
}

// round 9
// speedup vs baseline: 1.8505x; 1.0266x over previous
#include <cuda_runtime.h>
#include <cuda_bf16.h>
#include <math.h>
#include <stdint.h>

#define N_NODES 100000
#define N_EDGES 800000
#define N_NTILE 782
#define N_ETILE 6250

// bf16 tile image: 128 rows x 136 bf16 (272B stride); hi tile then lo tile
#define TROW 272
#define TBYTES 34816
#define IMGB 69632

// ---------------- device scratch ----------------
__device__ float g_h[(size_t)N_NODES * 128];
__device__ float g_q[(size_t)N_NODES * 128];
__device__ float g_k[(size_t)N_NODES * 128];
__device__ float g_v[(size_t)N_NODES * 128];
__device__ float g_skip[(size_t)N_NODES * 128];
__device__ float g_numer[(size_t)N_NODES * 128];
__device__ float g_denom[(size_t)N_NODES * 8];
__device__ unsigned char g_himg[(size_t)N_NTILE * IMGB];
__device__ unsigned char g_eaimg[(size_t)N_ETILE * IMGB];
__device__ unsigned char g_wimg[(size_t)15 * IMGB];
// sort scratch
__device__ int g_count[N_NODES];
__device__ int g_off2[N_NODES];
__device__ int g_src_s[N_EDGES];
__device__ int g_dst_s[N_EDGES];
__device__ int g_perm[N_EDGES];

// ---------------- PTX helpers ----------------
__device__ __forceinline__ uint32_t smem_u32(const void* p) {
    uint32_t a;
    asm("{ .reg .u64 t; cvta.to.shared.u64 t, %1; cvt.u32.u64 %0, t; }" : "=r"(a) : "l"(p));
    return a;
}
__device__ __forceinline__ void ldsm4(uint32_t* r, uint32_t addr) {
    asm volatile("ldmatrix.sync.aligned.m8n8.x4.shared.b16 {%0,%1,%2,%3}, [%4];"
                 : "=r"(r[0]), "=r"(r[1]), "=r"(r[2]), "=r"(r[3]) : "r"(addr));
}
__device__ __forceinline__ void mma16816(float* c, const uint32_t* a, uint32_t b0, uint32_t b1) {
    asm volatile("mma.sync.aligned.m16n8k16.row.col.f32.bf16.bf16.f32 "
                 "{%0,%1,%2,%3}, {%4,%5,%6,%7}, {%8,%9}, {%0,%1,%2,%3};"
                 : "+f"(c[0]), "+f"(c[1]), "+f"(c[2]), "+f"(c[3])
                 : "r"(a[0]), "r"(a[1]), "r"(a[2]), "r"(a[3]), "r"(b0), "r"(b1));
}
__device__ __forceinline__ void red_add4(float* addr, float a, float b, float c, float d) {
    asm volatile("red.global.add.v4.f32 [%0], {%1, %2, %3, %4};"
                 :: "l"(addr), "f"(a), "f"(b), "f"(c), "f"(d) : "memory");
}
__device__ __forceinline__ void cp_async16(uint32_t dst, const void* src) {
    asm volatile("cp.async.cg.shared.global [%0], [%1], 16;" :: "r"(dst), "l"(src));
}
#define CP_COMMIT() asm volatile("cp.async.commit_group;" ::: "memory")
#define CP_WAIT1()  asm volatile("cp.async.wait_group 1;" ::: "memory")
#define CP_WAIT0()  asm volatile("cp.async.wait_group 0;" ::: "memory")

__device__ __forceinline__ float pe_val(int t, int c) {
    int j = c >> 1;
    float freq = expf(-logf(10000.0f) * (float)(2 * j) * (1.0f / 16.0f));
    float ang = (float)t * freq;
    return (c & 1) ? cosf(ang) : sinf(ang);
}
__device__ __forceinline__ void split_store8(unsigned char* img, int off, const float* v) {
    unsigned int h[4], l[4];
#pragma unroll
    for (int i = 0; i < 4; ++i) {
        __nv_bfloat16 h0 = __float2bfloat16(v[2 * i]);
        __nv_bfloat16 h1 = __float2bfloat16(v[2 * i + 1]);
        __nv_bfloat16 l0 = __float2bfloat16(v[2 * i] - __bfloat162float(h0));
        __nv_bfloat16 l1 = __float2bfloat16(v[2 * i + 1] - __bfloat162float(h1));
        h[i] = (unsigned int)__bfloat16_as_ushort(h0) | ((unsigned int)__bfloat16_as_ushort(h1) << 16);
        l[i] = (unsigned int)__bfloat16_as_ushort(l0) | ((unsigned int)__bfloat16_as_ushort(l1) << 16);
    }
    *(uint4*)(img + off) = make_uint4(h[0], h[1], h[2], h[3]);
    *(uint4*)(img + TBYTES + off) = make_uint4(l[0], l[1], l[2], l[3]);
}

// 3-pass split-bf16 GEMM, 8-warp layout: warp (wr,wc) -> C[wr*32..+32][wc*64..+64]
__device__ __forceinline__ void gemm3(uint32_t aHi, uint32_t aLo, uint32_t bHi, uint32_t bLo,
                                      int lane, int wr, int wc, float c[2][8][4]) {
    int rA = lane & 15;
    int kA = (lane >> 4) << 3;
    int rB = ((lane >> 4) << 3) + (lane & 7);
    int kB = ((lane >> 3) & 1) << 3;
    uint32_t aRow = (uint32_t)(wr * 32 + rA) * TROW;
    uint32_t bRow = (uint32_t)(wc * 64 + rB) * TROW;
    for (int pass = 0; pass < 3; ++pass) {
        uint32_t aB = (pass < 2) ? aHi : aLo;
        uint32_t bB = (pass == 1) ? bLo : bHi;
#pragma unroll
        for (int k16 = 0; k16 < 8; ++k16) {
            uint32_t ka = (uint32_t)(k16 * 16 + kA) * 2;
            uint32_t kb = (uint32_t)(k16 * 16 + kB) * 2;
            uint32_t a[2][4];
            ldsm4(a[0], aB + aRow + ka);
            ldsm4(a[1], aB + aRow + 16 * TROW + ka);
            uint32_t b[4][4];
#pragma unroll
            for (int p = 0; p < 4; ++p) ldsm4(b[p], bB + bRow + p * 16 * TROW + kb);
#pragma unroll
            for (int t = 0; t < 2; ++t)
#pragma unroll
                for (int nt = 0; nt < 8; ++nt)
                    mma16816(c[t][nt], a[t], b[nt >> 1][(nt & 1) * 2], b[nt >> 1][(nt & 1) * 2 + 1]);
        }
    }
}

// 3-pass split-bf16 GEMM, 16-warp layout: warp (wr,wc) -> C[wr*32..+32][wc*32..+32]
__device__ __forceinline__ void gemm3w16(uint32_t aHi, uint32_t aLo, uint32_t bHi, uint32_t bLo,
                                         int lane, int wr, int wc, float c[2][4][4]) {
    int rA = lane & 15;
    int kA = (lane >> 4) << 3;
    int rB = ((lane >> 4) << 3) + (lane & 7);
    int kB = ((lane >> 3) & 1) << 3;
    uint32_t aRow = (uint32_t)(wr * 32 + rA) * TROW;
    uint32_t bRow = (uint32_t)(wc * 32 + rB) * TROW;
    for (int pass = 0; pass < 3; ++pass) {
        uint32_t aB = (pass < 2) ? aHi : aLo;
        uint32_t bB = (pass == 1) ? bLo : bHi;
#pragma unroll
        for (int k16 = 0; k16 < 8; ++k16) {
            uint32_t ka = (uint32_t)(k16 * 16 + kA) * 2;
            uint32_t kb = (uint32_t)(k16 * 16 + kB) * 2;
            uint32_t a[2][4];
            ldsm4(a[0], aB + aRow + ka);
            ldsm4(a[1], aB + aRow + 16 * TROW + ka);
            uint32_t b[2][4];
#pragma unroll
            for (int p = 0; p < 2; ++p) ldsm4(b[p], bB + bRow + p * 16 * TROW + kb);
#pragma unroll
            for (int t = 0; t < 2; ++t)
#pragma unroll
                for (int nt = 0; nt < 4; ++nt)
                    mma16816(c[t][nt], a[t], b[nt >> 1][(nt & 1) * 2], b[nt >> 1][(nt & 1) * 2 + 1]);
        }
    }
}

// ---------------- sort-by-dst ----------------
__global__ void zero_count_kernel() {
    int i = blockIdx.x * blockDim.x + threadIdx.x;
    if (i < N_NODES) g_count[i] = 0;
}
__global__ void hist_kernel(const int* __restrict__ ei) {
    int e = blockIdx.x * blockDim.x + threadIdx.x;
    if (e < N_EDGES) atomicAdd(&g_count[ei[N_EDGES + e]], 1);
}
__global__ void scan_kernel() {
    __shared__ int warp_sums[32];
    __shared__ int s_carry;
    int tid = threadIdx.x;
    int lane = tid & 31, wid = tid >> 5;
    if (tid == 0) s_carry = 0;
    __syncthreads();
    for (int base = 0; base < N_NODES; base += 1024) {
        int idx = base + tid;
        int v = (idx < N_NODES) ? g_count[idx] : 0;
        int inc = v;
#pragma unroll
        for (int o = 1; o < 32; o <<= 1) {
            int t = __shfl_up_sync(0xffffffffu, inc, o);
            if (lane >= o) inc += t;
        }
        if (lane == 31) warp_sums[wid] = inc;
        __syncthreads();
        if (wid == 0) {
            int w = warp_sums[lane];
            int wi = w;
#pragma unroll
            for (int o = 1; o < 32; o <<= 1) {
                int t = __shfl_up_sync(0xffffffffu, wi, o);
                if (lane >= o) wi += t;
            }
            warp_sums[lane] = wi - w;
        }
        __syncthreads();
        int ex = inc - v + warp_sums[wid] + s_carry;
        if (idx < N_NODES) g_off2[idx] = ex;
        __syncthreads();
        if (tid == 1023) s_carry = ex + v;
        __syncthreads();
    }
}
__global__ void scatter_kernel(const int* __restrict__ ei) {
    int e = blockIdx.x * blockDim.x + threadIdx.x;
    if (e >= N_EDGES) return;
    int d = ei[N_EDGES + e];
    int pos = atomicAdd(&g_off2[d], 1);
    g_src_s[pos] = ei[e];
    g_dst_s[pos] = d;
    g_perm[pos] = e;
}

// ---------------- builders ----------------
__global__ void build_h_kernel(const float* __restrict__ x, const int* __restrict__ nlu) {
    int gid = blockIdx.x * blockDim.x + threadIdx.x;
    if (gid >= N_NODES * 16) return;
    int n = gid >> 4, j = gid & 15, c0 = j * 8;
    float v[8];
    if (c0 < 96) {
        float4 a = *(const float4*)(x + (size_t)n * 96 + c0);
        float4 b = *(const float4*)(x + (size_t)n * 96 + c0 + 4);
        v[0] = a.x; v[1] = a.y; v[2] = a.z; v[3] = a.w; v[4] = b.x; v[5] = b.y; v[6] = b.z; v[7] = b.w;
    } else {
        int t = nlu[n * 2 + ((c0 - 96) >> 4)];
        int cl = (c0 - 96) & 15;
#pragma unroll
        for (int i = 0; i < 8; ++i) v[i] = pe_val(t, cl + i);
    }
    split_store8(g_himg + (size_t)(n >> 7) * IMGB, (n & 127) * TROW + c0 * 2, v);
}
__global__ void build_eaimg_kernel(const float* __restrict__ eattr, const int* __restrict__ elu) {
    int gid = blockIdx.x * blockDim.x + threadIdx.x;
    if (gid >= N_EDGES * 16) return;
    int p = gid >> 4, j = gid & 15, c0 = j * 8;
    int e = g_perm[p];
    float v[8];
    if (c0 < 96) {
        float4 a = *(const float4*)(eattr + (size_t)e * 96 + c0);
        float4 b = *(const float4*)(eattr + (size_t)e * 96 + c0 + 4);
        v[0] = a.x; v[1] = a.y; v[2] = a.z; v[3] = a.w; v[4] = b.x; v[5] = b.y; v[6] = b.z; v[7] = b.w;
    } else {
        int t = elu[(size_t)e * 2 + ((c0 - 96) >> 4)];
        int cl = (c0 - 96) & 15;
#pragma unroll
        for (int i = 0; i < 8; ++i) v[i] = pe_val(t, cl + i);
    }
    split_store8(g_eaimg + (size_t)(p >> 7) * IMGB, (p & 127) * TROW + c0 * 2, v);
}
__global__ void prep_w_kernel(const float* __restrict__ Wq, const float* __restrict__ Wk,
                              const float* __restrict__ Wv, const float* __restrict__ Ws,
                              const float* __restrict__ We) {
    int gid = blockIdx.x * blockDim.x + threadIdx.x;
    if (gid >= 15 * 2048) return;
    int t = gid >> 11, rem = gid & 2047;
    int n = rem >> 4, j = rem & 15, k0 = j * 8;
    int l = t / 5, m = t % 5;
    const float* W = (m == 0) ? Wq : (m == 1) ? Wk : (m == 2) ? Wv : (m == 3) ? Ws : We;
    const float* base = W + (size_t)l * 16384;
    float v[8];
#pragma unroll
    for (int i = 0; i < 8; ++i) v[i] = base[(size_t)(k0 + i) * 128 + n];
    split_store8(g_wimg + (size_t)t * IMGB, n * TROW + k0 * 2, v);
}

// ---------------- node GEMM (unchanged from round 8) ----------------
#define OFF_NB 69632
#define OFF_NBIAS 139264
#define SMEM_NODE 139776
__global__ __launch_bounds__(256, 1)
void node_mma_kernel(const float* __restrict__ bq, const float* __restrict__ bk,
                     const float* __restrict__ bv, const float* __restrict__ bsk, int layer) {
    extern __shared__ __align__(16) unsigned char smem[];
    uint32_t sb = smem_u32(smem);
    int tid = threadIdx.x, wid = tid >> 5, lane = tid & 31;
    int wr = wid & 3, wc = wid >> 2;
    int tile = blockIdx.x, ysel = blockIdx.y;
    int gi = lane >> 2, tig = lane & 3;

    const uint4* aimg = (const uint4*)(g_himg + (size_t)tile * IMGB);
    uint4* sA = (uint4*)smem;
#pragma unroll
    for (int it = 0; it < 17; ++it) sA[it * 256 + tid] = aimg[it * 256 + tid];

    float* biasBuf = (float*)(smem + OFF_NBIAS);
    uint4* sB = (uint4*)(smem + OFF_NB);

    for (int w2 = 0; w2 < 2; ++w2) {
        int w = ysel * 2 + w2;
        __syncthreads();
        const uint4* bimg = (const uint4*)(g_wimg + (size_t)(layer * 5 + w) * IMGB);
#pragma unroll
        for (int it = 0; it < 17; ++it) sB[it * 256 + tid] = bimg[it * 256 + tid];
        if (tid < 128) {
            const float* bias = (w == 0) ? bq : (w == 1) ? bk : (w == 2) ? bv : bsk;
            biasBuf[tid] = bias[layer * 128 + tid];
        }
        __syncthreads();

        float c[2][8][4];
#pragma unroll
        for (int t = 0; t < 2; ++t)
#pragma unroll
            for (int nt = 0; nt < 8; ++nt)
#pragma unroll
                for (int j = 0; j < 4; ++j) c[t][nt][j] = 0.0f;

        gemm3(sb, sb + TBYTES, sb + OFF_NB, sb + OFF_NB + TBYTES, lane, wr, wc, c);

        float* out = (w == 0) ? g_q : (w == 1) ? g_k : (w == 2) ? g_v : g_skip;
#pragma unroll
        for (int t = 0; t < 2; ++t) {
#pragma unroll
            for (int half = 0; half < 2; ++half) {
                int node = tile * 128 + wr * 32 + t * 16 + gi + half * 8;
                if (node < N_NODES) {
                    float* op = out + (size_t)node * 128;
#pragma unroll
                    for (int nt = 0; nt < 8; ++nt) {
                        int col = wc * 64 + nt * 8 + tig * 2;
                        *(float2*)(op + col) = make_float2(c[t][nt][half * 2 + 0] + biasBuf[col],
                                                           c[t][nt][half * 2 + 1] + biasBuf[col + 1]);
                    }
                }
            }
        }
    }
}

// ---------------- persistent fused edge kernel: 512 threads, double-buffered cp.async A ----------------
#define EB_B  0
#define EB_A0 69632
#define EB_A1 139264
#define EB_X  208896
#define SMEM_EDGE 209920
__global__ __launch_bounds__(512, 1)
void edge_mma_kernel(int layer) {
    extern __shared__ __align__(16) unsigned char smem[];
    uint32_t sb = smem_u32(smem);
    int tid = threadIdx.x, wid = tid >> 5, lane = tid & 31;
    int wr = wid & 3, wc = wid >> 2;
    int gi = lane >> 2, tig = lane & 3;
    int tx = tid & 15, ty = tid >> 4;
    int hd = tx >> 1, cb = tx << 3;

    // resident B (We image), loaded once
    const uint4* bimg = (const uint4*)(g_wimg + (size_t)(layer * 5 + 4) * IMGB);
    uint4* sB = (uint4*)smem;
    for (int i = tid; i < 4352; i += 512) sB[i] = bimg[i];

    int* s_src = (int*)(smem + EB_X);
    int* s_dst = (int*)(smem + EB_X + 512);

    // prefetch first A tile into buf0
    int tile0 = blockIdx.x;
    if (tile0 < N_ETILE) {
        const unsigned char* src = g_eaimg + (size_t)tile0 * IMGB;
        for (int i = tid; i < 4352; i += 512)
            cp_async16(sb + EB_A0 + i * 16, src + (size_t)i * 16);
    }
    CP_COMMIT();

    int cur = 0;
    for (int tile = tile0; tile < N_ETILE; tile += gridDim.x) {
        int next = tile + gridDim.x;
        uint32_t aBuf = sb + (cur ? EB_A1 : EB_A0);
        uint32_t aOther = sb + (cur ? EB_A0 : EB_A1);
        if (next < N_ETILE) {
            const unsigned char* src = g_eaimg + (size_t)next * IMGB;
            for (int i = tid; i < 4352; i += 512)
                cp_async16(aOther + i * 16, src + (size_t)i * 16);
            CP_COMMIT();
            CP_WAIT1();
        } else {
            CP_WAIT0();
        }
        __syncthreads();   // S1: A(cur) visible; prev epilogue done (for s_src/est safety)

        int e0 = tile << 7;
        if (tid < 128) {
            s_src[tid] = g_src_s[e0 + tid];
            s_dst[tid] = g_dst_s[e0 + tid];
        }

        float c[2][4][4];
#pragma unroll
        for (int t = 0; t < 2; ++t)
#pragma unroll
            for (int nt = 0; nt < 4; ++nt)
#pragma unroll
                for (int j = 0; j < 4; ++j) c[t][nt][j] = 0.0f;

        gemm3w16(aBuf, aBuf + TBYTES, sb + EB_B, sb + EB_B + TBYTES, lane, wr, wc, c);

        __syncthreads();   // S2: GEMM reads of A(cur) done -> est overlay safe
        float* est = (float*)(smem + (cur ? EB_A1 : EB_A0));
#pragma unroll
        for (int t = 0; t < 2; ++t)
#pragma unroll
            for (int half = 0; half < 2; ++half) {
                int r = wr * 32 + t * 16 + gi + half * 8;
#pragma unroll
                for (int nt = 0; nt < 4; ++nt) {
                    int col = wc * 32 + nt * 8 + tig * 2;
                    *(float2*)(est + r * 132 + col) = make_float2(c[t][nt][half * 2], c[t][nt][half * 2 + 1]);
                }
            }
        __syncthreads();   // S3: est + s_src/s_dst ready

        // run-coalesced softmax epilogue: 4 edges per thread
        int cur_d = -1;
        float aN0 = 0.f, aN1 = 0.f, aN2 = 0.f, aN3 = 0.f;
        float aN4 = 0.f, aN5 = 0.f, aN6 = 0.f, aN7 = 0.f;
        float aD = 0.f;
#pragma unroll
        for (int i = 0; i < 4; ++i) {
            int er = ty * 4 + i;
            float4 e0v = *(const float4*)(est + er * 132 + cb);
            float4 e1v = *(const float4*)(est + er * 132 + cb + 4);
            float e8[8] = {e0v.x, e0v.y, e0v.z, e0v.w, e1v.x, e1v.y, e1v.z, e1v.w};
            int s = s_src[er], d = s_dst[er];
            const float* qp = g_q + (size_t)d * 128 + cb;
            const float* kp = g_k + (size_t)s * 128 + cb;
            float4 q0 = *(const float4*)qp, q1 = *(const float4*)(qp + 4);
            float4 k0 = *(const float4*)kp, k1 = *(const float4*)(kp + 4);
            float part = q0.x * (k0.x + e8[0]) + q0.y * (k0.y + e8[1])
                       + q0.z * (k0.z + e8[2]) + q0.w * (k0.w + e8[3])
                       + q1.x * (k1.x + e8[4]) + q1.y * (k1.y + e8[5])
                       + q1.z * (k1.z + e8[6]) + q1.w * (k1.w + e8[7]);
            float full = part + __shfl_xor_sync(0xffffffffu, part, 1);
            float p = __expf(full * 0.25f);  // shift-free softmax (alpha is O(1))
            if (d != cur_d) {
                if (cur_d >= 0) {
                    float* np = g_numer + (size_t)cur_d * 128 + cb;
                    red_add4(np,     aN0, aN1, aN2, aN3);
                    red_add4(np + 4, aN4, aN5, aN6, aN7);
                    if (!(tx & 1)) atomicAdd(g_denom + (size_t)cur_d * 8 + hd, aD);
                }
                cur_d = d;
                aN0 = aN1 = aN2 = aN3 = aN4 = aN5 = aN6 = aN7 = 0.f;
                aD = 0.f;
            }
            const float* vp = g_v + (size_t)s * 128 + cb;
            float4 v0 = *(const float4*)vp, v1 = *(const float4*)(vp + 4);
            aN0 += p * (v0.x + e8[0]); aN1 += p * (v0.y + e8[1]);
            aN2 += p * (v0.z + e8[2]); aN3 += p * (v0.w + e8[3]);
            aN4 += p * (v1.x + e8[4]); aN5 += p * (v1.y + e8[5]);
            aN6 += p * (v1.z + e8[6]); aN7 += p * (v1.w + e8[7]);
            aD += p;
        }
        {
            float* np = g_numer + (size_t)cur_d * 128 + cb;
            red_add4(np,     aN0, aN1, aN2, aN3);
            red_add4(np + 4, aN4, aN5, aN6, aN7);
            if (!(tx & 1)) atomicAdd(g_denom + (size_t)cur_d * 8 + hd, aD);
        }
        cur ^= 1;
    }
}

// ---------------- node update ----------------
__global__ void update_h_kernel() {
    int gid = blockIdx.x * blockDim.x + threadIdx.x;
    if (gid >= N_NODES * 16) return;
    int n = gid >> 4, j = gid & 15, c0 = j * 8;
    float inv = 1.0f / (g_denom[n * 8 + (c0 >> 4)] + 1e-16f);
    float4 n0 = *(const float4*)(g_numer + (size_t)n * 128 + c0);
    float4 n1 = *(const float4*)(g_numer + (size_t)n * 128 + c0 + 4);
    float4 s0 = *(const float4*)(g_skip + (size_t)n * 128 + c0);
    float4 s1 = *(const float4*)(g_skip + (size_t)n * 128 + c0 + 4);
    float v[8];
    v[0] = fmaxf(n0.x * inv + s0.x, 0.f); v[1] = fmaxf(n0.y * inv + s0.y, 0.f);
    v[2] = fmaxf(n0.z * inv + s0.z, 0.f); v[3] = fmaxf(n0.w * inv + s0.w, 0.f);
    v[4] = fmaxf(n1.x * inv + s1.x, 0.f); v[5] = fmaxf(n1.y * inv + s1.y, 0.f);
    v[6] = fmaxf(n1.z * inv + s1.z, 0.f); v[7] = fmaxf(n1.w * inv + s1.w, 0.f);
    *(float4*)(g_h + (size_t)n * 128 + c0)     = make_float4(v[0], v[1], v[2], v[3]);
    *(float4*)(g_h + (size_t)n * 128 + c0 + 4) = make_float4(v[4], v[5], v[6], v[7]);
    split_store8(g_himg + (size_t)(n >> 7) * IMGB, (n & 127) * TROW + c0 * 2, v);
    float4 z = make_float4(0.f, 0.f, 0.f, 0.f);
    *(float4*)(g_numer + (size_t)n * 128 + c0)     = z;
    *(float4*)(g_numer + (size_t)n * 128 + c0 + 4) = z;
    if (!(j & 1)) g_denom[n * 8 + (j >> 1)] = 0.0f;
}

// ---------------- output GEMM ----------------
__global__ void out_gemm_kernel(const float* __restrict__ Wout, const float* __restrict__ bout,
                                float* __restrict__ out) {
    __shared__ float ws[128 * 16];
    __shared__ float hs[16 * 128];
    int tid = threadIdx.x;
    int row0 = blockIdx.x * 16;
#pragma unroll
    for (int it = 0; it < 8; ++it) {
        int idx = it * 256 + tid;
        ws[idx] = Wout[idx];
        int r = row0 + (idx >> 7);
        hs[idx] = (r < N_NODES) ? g_h[(size_t)row0 * 128 + idx] : 0.0f;
    }
    __syncthreads();
    int r = tid >> 4, c = tid & 15;
    float s = bout[c];
#pragma unroll 8
    for (int k = 0; k < 128; ++k) s += hs[r * 128 + k] * ws[k * 16 + c];
    int gr = row0 + r;
    if (gr < N_NODES) out[(size_t)gr * 16 + c] = s;
}

// ---------------- host ----------------
extern "C" void kernel_launch(void* const* d_in, const int* in_sizes, int n_in,
                              void* d_out, int out_size) {
    const float* x     = (const float*)d_in[0];
    const int*   nlu   = (const int*)  d_in[1];
    const int*   ei    = (const int*)  d_in[2];
    const float* eattr = (const float*)d_in[3];
    const int*   elu   = (const int*)  d_in[4];
    const float* Wq    = (const float*)d_in[5];
    const float* bq    = (const float*)d_in[6];
    const float* Wk    = (const float*)d_in[7];
    const float* bk    = (const float*)d_in[8];
    const float* Wv    = (const float*)d_in[9];
    const float* bv    = (const float*)d_in[10];
    const float* We    = (const float*)d_in[11];
    const float* Ws    = (const float*)d_in[12];
    const float* bs    = (const float*)d_in[13];
    const float* Wout  = (const float*)d_in[14];
    const float* bout  = (const float*)d_in[15];
    float* out = (float*)d_out;
    (void)in_sizes; (void)n_in; (void)out_size;

    cudaFuncSetAttribute(node_mma_kernel, cudaFuncAttributeMaxDynamicSharedMemorySize, SMEM_NODE);
    cudaFuncSetAttribute(edge_mma_kernel, cudaFuncAttributeMaxDynamicSharedMemorySize, SMEM_EDGE);

    zero_count_kernel<<<(N_NODES + 255) / 256, 256>>>();
    hist_kernel<<<(N_EDGES + 255) / 256, 256>>>(ei);
    scan_kernel<<<1, 1024>>>();
    scatter_kernel<<<(N_EDGES + 255) / 256, 256>>>(ei);

    build_h_kernel    <<<(N_NODES * 16 + 255) / 256, 256>>>(x, nlu);
    build_eaimg_kernel<<<(N_EDGES * 16 + 255) / 256, 256>>>(eattr, elu);
    prep_w_kernel     <<<(15 * 2048 + 255) / 256, 256>>>(Wq, Wk, Wv, Ws, We);

    for (int l = 0; l < 3; ++l) {
        node_mma_kernel<<<dim3(N_NTILE, 2), 256, SMEM_NODE>>>(bq, bk, bv, bs, l);
        edge_mma_kernel<<<148, 512, SMEM_EDGE>>>(l);
        update_h_kernel<<<(N_NODES * 16 + 255) / 256, 256>>>();
    }
    out_gemm_kernel<<<N_NODES / 16, 256>>>(Wout, bout, out);
}